// round 13
// baseline (speedup 1.0000x reference)
#include <cuda_runtime.h>
#include <cstdint>

#define DINL __device__ __forceinline__

constexpr int Tt = 96, Nn = 400, Fd = 256;
constexpr int Bb = 8;
constexpr int Mtot = Bb * Tt * Nn;              // 307200
constexpr int HEADS = Bb * Nn;                  // 3200
constexpr long BUF_ELEMS = (long)Mtot * Fd;     // 78,643,200

// ---------------- scratch (device globals; no allocation APIs) ----------------
__device__ float g_bufA[BUF_ELEMS];   // q row-major [B,N,T,F] -> preLN1/out1 fp32
__device__ float g_bufB[BUF_ELEMS];   // k row-major [B,N,T,F] -> preLN2 fp32
__device__ float g_bufC[BUF_ELEMS];   // v row-major [B,N,T,F]
__device__ float g_bufX[BUF_ELEMS];   // xl + te exact fp32 (residual)
__device__ float g_bufY[BUF_ELEMS];   // attention out row-major [B,T,N,F] (tf32)
// fragment-packed tf32 A-images: tiles of 64m x 32k = 2048 floats contiguous
__device__ float g_PX[BUF_ELEMS];     // packed xl+te
__device__ float g_PH[BUF_ELEMS];     // packed xh+te
__device__ float g_PO1[BUF_ELEMS];    // packed out1
__device__ float g_PHH[BUF_ELEMS];    // packed relu(ff1)
__device__ float g_bufW[6 * 256 * 256];  // packed tf32 weight fragments

// ---------------- tf32 + async-copy helpers ----------------
DINL uint32_t f2tf(float x) {
    uint32_t r;
    asm("cvt.rna.tf32.f32 %0, %1;" : "=r"(r) : "f"(x));
    return r;
}
DINL float tf2f(float x) { return __uint_as_float(f2tf(x)); }

DINL void mma8(float* c, const uint32_t* a, const uint32_t* b) {
    asm volatile(
        "mma.sync.aligned.m16n8k8.row.col.f32.tf32.tf32.f32 "
        "{%0,%1,%2,%3}, {%4,%5,%6,%7}, {%8,%9}, {%0,%1,%2,%3};"
        : "+f"(c[0]), "+f"(c[1]), "+f"(c[2]), "+f"(c[3])
        : "r"(a[0]), "r"(a[1]), "r"(a[2]), "r"(a[3]), "r"(b[0]), "r"(b[1]));
}

DINL void cpa16(float* smem_dst, const float* gsrc) {
    uint32_t d = (uint32_t)__cvta_generic_to_shared(smem_dst);
    asm volatile("cp.async.cg.shared.global [%0], [%1], 16;\n" :: "r"(d), "l"(gsrc));
}
#define CP_COMMIT()  asm volatile("cp.async.commit_group;\n")
#define CP_WAIT(n)   asm volatile("cp.async.wait_group %0;\n" :: "n"(n))

// packed-tile inner offset for (mrow in [0,64), kc32 in [0,32))
DINL int pk_off(int mrow, int kc32) {
    int mi = mrow >> 4, r = mrow & 15, kii = kc32 >> 3, kc = kc32 & 7;
    return ((mi * 4 + kii) * 32 + (r & 7) * 4 + (kc & 3)) * 4 + (r >> 3) + ((kc >> 2) << 1);
}

// =====================================================================
// Pre-pass (tile-based, coalesced packed writes)
// =====================================================================
__global__ __launch_bounds__(256) void prep_x(
    const float* __restrict__ xl, const float* __restrict__ xh,
    const float* __restrict__ te)
{
    __shared__ float sX[2048], sH[2048];
    const int mt = blockIdx.x, m0 = mt * 64, tid = threadIdx.x;
    for (int ks = 0; ks < 8; ks++) {
#pragma unroll
        for (int j = 0; j < 2; j++) {
            int cc = j * 256 + tid;          // 0..511
            int r = cc >> 3, c4 = cc & 7;
            int m = m0 + r;
            long g = (long)m * 256 + ks * 32 + c4 * 4;
            int bt = m / Nn;
            float4 t4 = *(const float4*)(te + bt * 256 + ks * 32 + c4 * 4);
            float4 a = *(const float4*)(xl + g);
            float4 b = *(const float4*)(xh + g);
            a.x += t4.x; a.y += t4.y; a.z += t4.z; a.w += t4.w;
            b.x += t4.x; b.y += t4.y; b.z += t4.z; b.w += t4.w;
            *(float4*)(g_bufX + g) = a;
            int k0 = c4 * 4;
            sX[pk_off(r, k0 + 0)] = tf2f(a.x); sX[pk_off(r, k0 + 1)] = tf2f(a.y);
            sX[pk_off(r, k0 + 2)] = tf2f(a.z); sX[pk_off(r, k0 + 3)] = tf2f(a.w);
            sH[pk_off(r, k0 + 0)] = tf2f(b.x); sH[pk_off(r, k0 + 1)] = tf2f(b.y);
            sH[pk_off(r, k0 + 2)] = tf2f(b.z); sH[pk_off(r, k0 + 3)] = tf2f(b.w);
        }
        __syncthreads();
        long base = ((long)mt * 8 + ks) * 2048;
#pragma unroll
        for (int j = 0; j < 2; j++) {
            int idx = j * 256 + tid;
            *(float4*)(g_PX + base + idx * 4) = *(const float4*)(sX + idx * 4);
            *(float4*)(g_PH + base + idx * 4) = *(const float4*)(sH + idx * 4);
        }
        __syncthreads();
    }
}

// =====================================================================
// Pack all 6 weights [256x256] (W[n][k]) into B fragment layout.
// =====================================================================
__global__ __launch_bounds__(256) void pack_w6(
    const float* __restrict__ W0, const float* __restrict__ W1,
    const float* __restrict__ W2, const float* __restrict__ W3,
    const float* __restrict__ W4, const float* __restrict__ W5)
{
    int widx = blockIdx.x >> 8;
    const float* W;
    switch (widx) {
        case 0: W = W0; break;
        case 1: W = W1; break;
        case 2: W = W2; break;
        case 3: W = W3; break;
        case 4: W = W4; break;
        default: W = W5; break;
    }
    int i = (blockIdx.x & 255) * 256 + threadIdx.x;  // 0..65535
    int n = i >> 8, k = i & 255;
    int kb = k >> 3, nb = n >> 3;
    int lanei = (n & 7) * 4 + (k & 3);
    int reg = (k >> 2) & 1;
    g_bufW[widx * 65536 + ((kb * 32 + nb) * 32 + lanei) * 2 + reg] = tf2f(W[i]);
}

// =====================================================================
// GEMM v7 (packed A): BM=128, BN=256, BK=32. 256 thr = 8 warps (2m x 4n),
// warp tile 64x64 (128 accum regs). grid 2400. Tensor-bound by design.
// =====================================================================
constexpr int A2_TILE = 4096;                    // 2 packed m-tiles x 32k
constexpr int B2_TILE = 8192;                    // full 32k x 256n W slice
constexpr int GEMM_SMEM_P = (2 * B2_TILE + 2 * A2_TILE) * 4;   // 98304

__global__ __launch_bounds__(256, 1) void gemm_p(
    const float* __restrict__ Apk, const float* __restrict__ Wp,
    const float* __restrict__ bias, const float* __restrict__ R,
    float* __restrict__ Ofp, float* __restrict__ Opk,
    int relu, int trans, int docvt)
{
    extern __shared__ float sm[];
    float* Bs = sm;                      // 2 x 8192
    float* As = sm + 2 * B2_TILE;        // 2 x 4096

    const int tid = threadIdx.x;
    const int lane = tid & 31, wid = tid >> 5;
    const int wm = wid & 1;                      // 2 m-warps
    const int wn = wid >> 1;                     // 4 n-warps
    const int bx = blockIdx.x;
    const int m0 = bx * 128;
    const float* Abase = Apk + (long)bx * 32768; // 2 m-tiles x 8 slices x 2048

    auto stage = [&](int kt, int b) {
        float* adst = As + b * A2_TILE;
        const float* a0 = Abase + kt * 2048;
        const float* a1 = Abase + 16384 + kt * 2048;
#pragma unroll
        for (int j = 0; j < 2; j++) {
            int c = j * 256 + tid;               // 0..511 float4
            cpa16(adst + c * 4, a0 + c * 4);
            cpa16(adst + 2048 + c * 4, a1 + c * 4);
        }
        const float* bsrc = Wp + kt * 8192;      // contiguous slice
        float* bdst = Bs + b * B2_TILE;
#pragma unroll
        for (int j = 0; j < 8; j++) {
            int c = j * 256 + tid;
            cpa16(bdst + c * 4, bsrc + c * 4);
        }
        CP_COMMIT();
    };

    float c[4][8][4];
#pragma unroll
    for (int i = 0; i < 4; i++)
#pragma unroll
        for (int j = 0; j < 8; j++)
#pragma unroll
            for (int k2 = 0; k2 < 4; k2++) c[i][j][k2] = 0.f;

    stage(0, 0);

    for (int kt = 0; kt < 8; kt++) {
        if (kt < 7) stage(kt + 1, (kt + 1) & 1);
        if (kt < 7) { CP_WAIT(1); } else { CP_WAIT(0); }
        __syncthreads();

        const float* Ab = As + (kt & 1) * A2_TILE + wm * 2048;
        const float* Bb = Bs + (kt & 1) * B2_TILE;
#pragma unroll
        for (int ks = 0; ks < 4; ks++) {
            uint32_t a[4][4];
#pragma unroll
            for (int im = 0; im < 4; im++) {
                float4 av = *(const float4*)(Ab + ((im * 4 + ks) * 32 + lane) * 4);
                a[im][0] = __float_as_uint(av.x); a[im][1] = __float_as_uint(av.y);
                a[im][2] = __float_as_uint(av.z); a[im][3] = __float_as_uint(av.w);
            }
#pragma unroll
            for (int in = 0; in < 8; in++) {
                const float2 bv = *(const float2*)&Bb[((ks * 32 + wn * 8 + in) * 32 + lane) * 2];
                uint32_t b[2] = { __float_as_uint(bv.x), __float_as_uint(bv.y) };
#pragma unroll
                for (int im = 0; im < 4; im++) mma8(c[im][in], a[im], b);
            }
        }
        __syncthreads();
    }

    if (Ofp) {
#pragma unroll
        for (int im = 0; im < 4; im++) {
#pragma unroll
            for (int h = 0; h < 2; h++) {
                int row = m0 + wm * 64 + im * 16 + (lane >> 2) + h * 8;
                long ob;
                if (trans) {
                    int bt = row / Nn;
                    int nidx = row - bt * Nn;
                    int t = bt % Tt, bbi = bt / Tt;
                    ob = ((long)(bbi * Nn + nidx) * Tt + t) * 256;
                } else {
                    ob = (long)row * 256;
                }
#pragma unroll
                for (int in = 0; in < 8; in++) {
                    int col = wn * 64 + in * 8 + (lane & 3) * 2;
                    float v0 = c[im][in][h * 2 + 0] + bias[col];
                    float v1 = c[im][in][h * 2 + 1] + bias[col + 1];
                    if (R) {
                        v0 += R[(long)row * 256 + col];
                        v1 += R[(long)row * 256 + col + 1];
                    }
                    if (relu) { v0 = fmaxf(v0, 0.f); v1 = fmaxf(v1, 0.f); }
                    if (docvt) { v0 = tf2f(v0); v1 = tf2f(v1); }
                    *(float2*)(Ofp + ob + col) = make_float2(v0, v1);
                }
            }
        }
    }
    if (Opk) {   // packed output, two-phase smem staging (one 64-row m-tile each)
#pragma unroll
        for (int p = 0; p < 2; p++) {
            __syncthreads();
            if (wm == p) {
#pragma unroll
                for (int im = 0; im < 4; im++)
#pragma unroll
                    for (int h = 0; h < 2; h++) {
                        int mrow = im * 16 + (lane >> 2) + h * 8;
#pragma unroll
                        for (int in = 0; in < 8; in++) {
                            int col = wn * 64 + in * 8 + (lane & 3) * 2;
                            float v0 = c[im][in][h * 2 + 0] + bias[col];
                            float v1 = c[im][in][h * 2 + 1] + bias[col + 1];
                            if (relu) { v0 = fmaxf(v0, 0.f); v1 = fmaxf(v1, 0.f); }
                            int off = (col >> 5) * 2048 + pk_off(mrow, col & 31);
                            sm[off]     = tf2f(v0);
                            sm[off + 4] = tf2f(v1);
                        }
                    }
            }
            __syncthreads();
            long base = (long)(bx * 2 + p) * 16384;
#pragma unroll
            for (int j = 0; j < 16; j++) {
                int idx = j * 256 + tid;         // float4 idx 0..4095
                *(float4*)(Opk + base + idx * 4) = *(const float4*)(sm + idx * 4);
            }
        }
    }
}

// =====================================================================
// GEMM v7 (row-major A, for Wo on attention output): same 128x256 shape.
// =====================================================================
constexpr int AR_STRIDE = 36;
constexpr int AR_TILE = 128 * AR_STRIDE;         // 4608
constexpr int GEMM_SMEM_R = (2 * B2_TILE + 2 * AR_TILE) * 4;  // 102400

__global__ __launch_bounds__(256, 1) void gemm_r(
    const float* __restrict__ Arow, const float* __restrict__ Wp,
    const float* __restrict__ bias, const float* __restrict__ R,
    float* __restrict__ Ofp)
{
    extern __shared__ float sm[];
    float* Bs = sm;                      // 2 x 8192
    float* As = sm + 2 * B2_TILE;        // 2 x 4608

    const int tid = threadIdx.x;
    const int lane = tid & 31, wid = tid >> 5;
    const int wm = wid & 1;
    const int wn = wid >> 1;
    const int m0 = blockIdx.x * 128;

    auto stage = [&](int kt, int b) {
        const float* asrc = Arow + (long)m0 * 256 + kt * 32;
        float* adst = As + b * AR_TILE;
#pragma unroll
        for (int j = 0; j < 4; j++) {
            int cc = j * 256 + tid;              // 0..1023
            int row = cc >> 3, c4 = cc & 7;
            cpa16(adst + row * AR_STRIDE + c4 * 4, asrc + (long)row * 256 + c4 * 4);
        }
        const float* bsrc = Wp + kt * 8192;
        float* bdst = Bs + b * B2_TILE;
#pragma unroll
        for (int j = 0; j < 8; j++) {
            int c = j * 256 + tid;
            cpa16(bdst + c * 4, bsrc + c * 4);
        }
        CP_COMMIT();
    };

    float c[4][8][4];
#pragma unroll
    for (int i = 0; i < 4; i++)
#pragma unroll
        for (int j = 0; j < 8; j++)
#pragma unroll
            for (int k2 = 0; k2 < 4; k2++) c[i][j][k2] = 0.f;

    stage(0, 0);

    for (int kt = 0; kt < 8; kt++) {
        if (kt < 7) stage(kt + 1, (kt + 1) & 1);
        if (kt < 7) { CP_WAIT(1); } else { CP_WAIT(0); }
        __syncthreads();

        const float* Ab = As + (kt & 1) * AR_TILE;
        const float* Bb = Bs + (kt & 1) * B2_TILE;
#pragma unroll
        for (int ks = 0; ks < 4; ks++) {
            uint32_t a[4][4];
#pragma unroll
            for (int im = 0; im < 4; im++) {
                const float* ap = Ab + (wm * 64 + im * 16 + (lane >> 2)) * AR_STRIDE
                                     + ks * 8 + (lane & 3);
                a[im][0] = __float_as_uint(ap[0]);
                a[im][1] = __float_as_uint(ap[8 * AR_STRIDE]);
                a[im][2] = __float_as_uint(ap[4]);
                a[im][3] = __float_as_uint(ap[8 * AR_STRIDE + 4]);
            }
#pragma unroll
            for (int in = 0; in < 8; in++) {
                const float2 bv = *(const float2*)&Bb[((ks * 32 + wn * 8 + in) * 32 + lane) * 2];
                uint32_t b[2] = { __float_as_uint(bv.x), __float_as_uint(bv.y) };
#pragma unroll
                for (int im = 0; im < 4; im++) mma8(c[im][in], a[im], b);
            }
        }
        __syncthreads();
    }

#pragma unroll
    for (int im = 0; im < 4; im++) {
#pragma unroll
        for (int h = 0; h < 2; h++) {
            int row = m0 + wm * 64 + im * 16 + (lane >> 2) + h * 8;
            long ob = (long)row * 256;
#pragma unroll
            for (int in = 0; in < 8; in++) {
                int col = wn * 64 + in * 8 + (lane & 3) * 2;
                float v0 = c[im][in][h * 2 + 0] + bias[col] + R[(long)row * 256 + col];
                float v1 = c[im][in][h * 2 + 1] + bias[col + 1] + R[(long)row * 256 + col + 1];
                *(float2*)(Ofp + ob + col) = make_float2(v0, v1);
            }
        }
    }
}

// =====================================================================
// Fused attention: S=q@k^T in smem, masked softmax, O=P@V -> bufY row-major
// =====================================================================
constexpr int S_STRIDE = 100;
constexpr int ATTN_SMEM = (96 * S_STRIDE + 6144) * 4;  // 62976 B

__global__ __launch_bounds__(256) void attn_fused() {
    extern __shared__ float sm[];
    float* S = sm;
    float* As = sm + 96 * S_STRIDE;
    float* Bs = As + 3072;
    float* Vs = As;

    const int head = blockIdx.x;
    const int tid = threadIdx.x, lane = tid & 31, wid = tid >> 5;
    const int wm = wid & 1, wn = wid >> 1;
    const float* qh = g_bufA + (long)head * (Tt * 256);
    const float* kh = g_bufB + (long)head * (Tt * 256);
    const float* vh = g_bufC + (long)head * (Tt * 256);

    {
        float c[3][3][4] = {};
        for (int kt = 0; kt < 256; kt += 32) {
#pragma unroll
            for (int j = 0; j < 3; j++) {
                int idx = j * 256 + tid;
                int ar = idx >> 3, ac4 = idx & 7;
                float4 v = *(const float4*)(qh + ar * 256 + kt + ac4 * 4);
                int mi = ar >> 4, r = ar & 15;
                int kii = ac4 >> 1, regb = (r >> 3) + ((ac4 & 1) << 1);
                float* dst = &As[((mi * 4 + kii) * 32 + (r & 7) * 4) * 4 + regb];
                dst[0] = v.x; dst[4] = v.y; dst[8] = v.z; dst[12] = v.w;
            }
#pragma unroll
            for (int j = 0; j < 3; j++) {
                int idx = j * 256 + tid;
                int br = idx >> 3, bc4 = idx & 7;
                float4 v = *(const float4*)(kh + br * 256 + kt + bc4 * 4);
                int ni = br >> 3, nr = br & 7;
                int kii = bc4 >> 1, regb = bc4 & 1;
                float* dst = &Bs[((ni * 4 + kii) * 32 + nr * 4) * 2 + regb];
                dst[0] = v.x; dst[2] = v.y; dst[4] = v.z; dst[6] = v.w;
            }
            __syncthreads();
#pragma unroll
            for (int ks = 0; ks < 4; ks++) {
                uint32_t a[3][4], b[3][2];
#pragma unroll
                for (int im = 0; im < 3; im++) {
                    float4 av = *(const float4*)&As[(((wm * 3 + im) * 4 + ks) * 32 + lane) * 4];
                    a[im][0] = __float_as_uint(av.x); a[im][1] = __float_as_uint(av.y);
                    a[im][2] = __float_as_uint(av.z); a[im][3] = __float_as_uint(av.w);
                }
#pragma unroll
                for (int in = 0; in < 3; in++) {
                    float2 bv = *(const float2*)&Bs[(((wn * 3 + in) * 4 + ks) * 32 + lane) * 2];
                    b[in][0] = __float_as_uint(bv.x); b[in][1] = __float_as_uint(bv.y);
                }
#pragma unroll
                for (int im = 0; im < 3; im++)
#pragma unroll
                    for (int in = 0; in < 3; in++)
                        mma8(c[im][in], a[im], b[in]);
            }
            __syncthreads();
        }
#pragma unroll
        for (int im = 0; im < 3; im++)
#pragma unroll
            for (int h = 0; h < 2; h++) {
                int row = wm * 48 + im * 16 + (lane >> 2) + h * 8;
#pragma unroll
                for (int in = 0; in < 3; in++) {
                    int col = wn * 24 + in * 8 + (lane & 3) * 2;
                    *(float2*)(S + row * S_STRIDE + col) =
                        make_float2(c[im][in][h * 2], c[im][in][h * 2 + 1]);
                }
            }
    }
    __syncthreads();

#pragma unroll
    for (int r = 0; r < 12; r++) {
        int row = wid * 12 + r;
        float* p = S + row * S_STRIDE;
        float x[3];
#pragma unroll
        for (int j = 0; j < 3; j++) {
            int col = lane + j * 32;
            float s = p[col];
            x[j] = (col <= row) ? s * 0.0625f : (-32767.0f * 0.0625f);
        }
        float mx = fmaxf(x[0], fmaxf(x[1], x[2]));
#pragma unroll
        for (int o = 16; o > 0; o >>= 1) mx = fmaxf(mx, __shfl_xor_sync(0xffffffffu, mx, o));
        float e0 = __expf(x[0] - mx), e1 = __expf(x[1] - mx), e2 = __expf(x[2] - mx);
        float sum = e0 + e1 + e2;
#pragma unroll
        for (int o = 16; o > 0; o >>= 1) sum += __shfl_xor_sync(0xffffffffu, sum, o);
        float inv = 1.0f / sum;
        p[lane]      = tf2f(e0 * inv);
        p[lane + 32] = tf2f(e1 * inv);
        p[lane + 64] = tf2f(e2 * inv);
    }
    __syncthreads();

    const int bbi = head / Nn, nh = head % Nn;
    for (int n0 = 0; n0 < 256; n0 += 64) {
#pragma unroll
        for (int j = 0; j < 6; j++) {
            int idx = j * 256 + tid;
            int sr = idx >> 4, f4 = idx & 15;
            float4 vv = *(const float4*)(vh + sr * 256 + n0 + f4 * 4);
            int kt = sr >> 5, srl = sr & 31;
            int ni = f4 >> 1;
            int kii = srl >> 3;
            int regb = (srl >> 2) & 1;
            int lb = (f4 & 1) * 16 + (srl & 3);
            float* dst = &Vs[kt * 2048 + ((ni * 4 + kii) * 32) * 2 + regb];
            dst[(lb + 0) * 2]  = vv.x;
            dst[(lb + 4) * 2]  = vv.y;
            dst[(lb + 8) * 2]  = vv.z;
            dst[(lb + 12) * 2] = vv.w;
        }
        __syncthreads();

        float c[3][2][4] = {};
#pragma unroll
        for (int kt = 0; kt < 3; kt++) {
#pragma unroll
            for (int ks = 0; ks < 4; ks++) {
                uint32_t a[3][4], b[2][2];
#pragma unroll
                for (int im = 0; im < 3; im++) {
                    const float* ap = S + (wm * 48 + im * 16 + (lane >> 2)) * S_STRIDE
                                        + kt * 32 + ks * 8 + (lane & 3);
                    a[im][0] = __float_as_uint(ap[0]);
                    a[im][1] = __float_as_uint(ap[8 * S_STRIDE]);
                    a[im][2] = __float_as_uint(ap[4]);
                    a[im][3] = __float_as_uint(ap[8 * S_STRIDE + 4]);
                }
#pragma unroll
                for (int in = 0; in < 2; in++) {
                    float2 bv = *(const float2*)&Vs[kt * 2048 +
                        (((wn * 2 + in) * 4 + ks) * 32 + lane) * 2];
                    b[in][0] = __float_as_uint(bv.x); b[in][1] = __float_as_uint(bv.y);
                }
#pragma unroll
                for (int im = 0; im < 3; im++)
#pragma unroll
                    for (int in = 0; in < 2; in++)
                        mma8(c[im][in], a[im], b[in]);
            }
        }
#pragma unroll
        for (int im = 0; im < 3; im++)
#pragma unroll
            for (int h = 0; h < 2; h++) {
                int t = wm * 48 + im * 16 + (lane >> 2) + h * 8;
                long ob = ((long)(bbi * Tt + t) * Nn + nh) * 256;
#pragma unroll
                for (int in = 0; in < 2; in++) {
                    int f = n0 + wn * 16 + in * 8 + (lane & 3) * 2;
                    *(float2*)(g_bufY + ob + f) =
                        make_float2(tf2f(c[im][in][h * 2]), tf2f(c[im][in][h * 2 + 1]));
                }
            }
        __syncthreads();
    }
}

// =====================================================================
// LN1 with coalesced packed output: 64 rows per CTA, 64KB smem tile.
// =====================================================================
constexpr int LNP_SMEM = 16384 * 4;

__global__ __launch_bounds__(256) void ln_pack(
    const float* __restrict__ in, float* __restrict__ outfp,
    float* __restrict__ outpk)
{
    extern __shared__ float sm[];
    const int mt = blockIdx.x, tid = threadIdx.x;
    const int lane = tid & 31, wid = tid >> 5;
#pragma unroll
    for (int i = 0; i < 8; i++) {
        int mrow = wid * 8 + i;
        long row = (long)mt * 64 + mrow;
        const float* p = in + row * 256;
        float4 a = *(const float4*)(p + lane * 4);
        float4 b = *(const float4*)(p + 128 + lane * 4);
        float s = a.x + a.y + a.z + a.w + b.x + b.y + b.z + b.w;
        float q = a.x * a.x + a.y * a.y + a.z * a.z + a.w * a.w +
                  b.x * b.x + b.y * b.y + b.z * b.z + b.w * b.w;
#pragma unroll
        for (int o = 16; o > 0; o >>= 1) {
            s += __shfl_xor_sync(0xffffffffu, s, o);
            q += __shfl_xor_sync(0xffffffffu, q, o);
        }
        float mean = s * (1.0f / 256.0f);
        float var = q * (1.0f / 256.0f) - mean * mean;
        float rs = rsqrtf(var + 1e-5f);
        float4 oa = make_float4((a.x - mean) * rs, (a.y - mean) * rs,
                                (a.z - mean) * rs, (a.w - mean) * rs);
        float4 ob = make_float4((b.x - mean) * rs, (b.y - mean) * rs,
                                (b.z - mean) * rs, (b.w - mean) * rs);
        float* op = outfp + row * 256;
        *(float4*)(op + lane * 4) = oa;
        *(float4*)(op + 128 + lane * 4) = ob;
        int ksA = lane >> 3, kc = (lane & 7) * 4;
        float* sA = sm + ksA * 2048;
        sA[pk_off(mrow, kc + 0)] = tf2f(oa.x); sA[pk_off(mrow, kc + 1)] = tf2f(oa.y);
        sA[pk_off(mrow, kc + 2)] = tf2f(oa.z); sA[pk_off(mrow, kc + 3)] = tf2f(oa.w);
        float* sB = sm + (4 + ksA) * 2048;
        sB[pk_off(mrow, kc + 0)] = tf2f(ob.x); sB[pk_off(mrow, kc + 1)] = tf2f(ob.y);
        sB[pk_off(mrow, kc + 2)] = tf2f(ob.z); sB[pk_off(mrow, kc + 3)] = tf2f(ob.w);
    }
    __syncthreads();
    long base = (long)mt * 16384;
#pragma unroll
    for (int j = 0; j < 16; j++) {
        int idx = j * 256 + tid;
        *(float4*)(outpk + base + idx * 4) = *(const float4*)(sm + idx * 4);
    }
}

// =====================================================================
// Final LayerNorm (fp32 out only).
// =====================================================================
__global__ __launch_bounds__(256) void ln_k(
    const float* __restrict__ in, float* __restrict__ outfp)
{
    long row = (long)blockIdx.x * 8 + (threadIdx.x >> 5);
    int lane = threadIdx.x & 31;
    const float* p = in + row * 256;
    float4 a = *(const float4*)(p + lane * 4);
    float4 b = *(const float4*)(p + 128 + lane * 4);
    float s = a.x + a.y + a.z + a.w + b.x + b.y + b.z + b.w;
    float q = a.x * a.x + a.y * a.y + a.z * a.z + a.w * a.w +
              b.x * b.x + b.y * b.y + b.z * b.z + b.w * b.w;
#pragma unroll
    for (int o = 16; o > 0; o >>= 1) {
        s += __shfl_xor_sync(0xffffffffu, s, o);
        q += __shfl_xor_sync(0xffffffffu, q, o);
    }
    float mean = s * (1.0f / 256.0f);
    float var = q * (1.0f / 256.0f) - mean * mean;
    float rs = rsqrtf(var + 1e-5f);
    float* op = outfp + row * 256;
    *(float4*)(op + lane * 4) =
        make_float4((a.x - mean) * rs, (a.y - mean) * rs, (a.z - mean) * rs, (a.w - mean) * rs);
    *(float4*)(op + 128 + lane * 4) =
        make_float4((b.x - mean) * rs, (b.y - mean) * rs, (b.z - mean) * rs, (b.w - mean) * rs);
}

// =====================================================================
extern "C" void kernel_launch(void* const* d_in, const int* in_sizes, int n_in,
                              void* d_out, int out_size) {
    const float* xl  = (const float*)d_in[0];
    const float* xh  = (const float*)d_in[1];
    const float* te  = (const float*)d_in[2];
    const float* Wq  = (const float*)d_in[3];
    const float* bq  = (const float*)d_in[4];
    const float* Wk  = (const float*)d_in[5];
    const float* bk  = (const float*)d_in[6];
    const float* Wv  = (const float*)d_in[7];
    const float* bv  = (const float*)d_in[8];
    const float* Wo  = (const float*)d_in[9];
    const float* bo  = (const float*)d_in[10];
    const float* Wf1 = (const float*)d_in[11];
    const float* bf1 = (const float*)d_in[12];
    const float* Wf2 = (const float*)d_in[13];
    const float* bf2 = (const float*)d_in[14];
    float* out = (float*)d_out;

    static bool init = false;
    static float *wbase, *bA, *bB, *bC, *bX, *bY, *pX, *pH, *pO1, *pHH;
    if (!init) {
        cudaFuncSetAttribute(gemm_p, cudaFuncAttributeMaxDynamicSharedMemorySize, GEMM_SMEM_P);
        cudaFuncSetAttribute(gemm_r, cudaFuncAttributeMaxDynamicSharedMemorySize, GEMM_SMEM_R);
        cudaFuncSetAttribute(attn_fused, cudaFuncAttributeMaxDynamicSharedMemorySize, ATTN_SMEM);
        cudaFuncSetAttribute(ln_pack, cudaFuncAttributeMaxDynamicSharedMemorySize, LNP_SMEM);
        cudaGetSymbolAddress((void**)&wbase, g_bufW);
        cudaGetSymbolAddress((void**)&bA, g_bufA);
        cudaGetSymbolAddress((void**)&bB, g_bufB);
        cudaGetSymbolAddress((void**)&bC, g_bufC);
        cudaGetSymbolAddress((void**)&bX, g_bufX);
        cudaGetSymbolAddress((void**)&bY, g_bufY);
        cudaGetSymbolAddress((void**)&pX, g_PX);
        cudaGetSymbolAddress((void**)&pH, g_PH);
        cudaGetSymbolAddress((void**)&pO1, g_PO1);
        cudaGetSymbolAddress((void**)&pHH, g_PHH);
        init = true;
    }

    prep_x<<<Mtot / 64, 256>>>(xl, xh, te);
    pack_w6<<<1536, 256>>>(Wq, Wk, Wv, Wo, Wf1, Wf2);

    dim3 gg(Mtot / 128);   // 2400 CTAs per dense GEMM

    // q = X @ Wq^T + bq            -> bufA row-major [B,N,T,F], tf32-rounded
    gemm_p<<<gg, 256, GEMM_SMEM_P>>>(pX, wbase + 0 * 65536, bq, nullptr, bA, nullptr, 0, 1, 1);
    // k = relu(H @ Wk^T + bk)      -> bufB
    gemm_p<<<gg, 256, GEMM_SMEM_P>>>(pH, wbase + 1 * 65536, bk, nullptr, bB, nullptr, 1, 1, 1);
    // v = relu(H @ Wv^T + bv)      -> bufC
    gemm_p<<<gg, 256, GEMM_SMEM_P>>>(pH, wbase + 2 * 65536, bv, nullptr, bC, nullptr, 1, 1, 1);

    attn_fused<<<HEADS, 256, ATTN_SMEM>>>();       // -> bufY row-major (tf32)

    // preLN1 = Y @ Wo^T + bo + X   -> bufA fp32 row-major
    gemm_r<<<gg, 256, GEMM_SMEM_R>>>(bY, wbase + 3 * 65536, bo, bX, bA);
    // out1 = LN(preLN1)            -> bufA fp32 (in place) + pO1 packed
    ln_pack<<<Mtot / 64, 256, LNP_SMEM>>>(bA, bA, pO1);

    // h = relu(out1 @ Wf1^T + bf1) -> pHH packed only
    gemm_p<<<gg, 256, GEMM_SMEM_P>>>(pO1, wbase + 4 * 65536, bf1, nullptr, nullptr, pHH, 1, 0, 0);
    // preLN2 = h @ Wf2^T + bf2 + out1 -> bufB fp32
    gemm_p<<<gg, 256, GEMM_SMEM_P>>>(pHH, wbase + 5 * 65536, bf2, bA, bB, nullptr, 0, 0, 0);
    ln_k<<<Mtot / 8, 256>>>(bB, out);              // final LN -> d_out
}

// round 15
// speedup vs baseline: 1.0061x; 1.0061x over previous
#include <cuda_runtime.h>
#include <cstdint>

#define DINL __device__ __forceinline__

constexpr int Tt = 96, Nn = 400, Fd = 256;
constexpr int Bb = 8;
constexpr int Mtot = Bb * Tt * Nn;              // 307200
constexpr int HEADS = Bb * Nn;                  // 3200
constexpr long BUF_ELEMS = (long)Mtot * Fd;     // 78,643,200

// ---------------- scratch (device globals; no allocation APIs) ----------------
__device__ float g_bufA[BUF_ELEMS];   // q [B,N,T,F] -> preLN1 -> out1 fp32
__device__ float g_bufB[BUF_ELEMS];   // k [B,N,T,F] -> preLN2 fp32
__device__ float g_bufC[BUF_ELEMS];   // v [B,N,T,F]
__device__ float g_bufX[BUF_ELEMS];   // tf32(xl + te) row-major (residual + q-GEMM A)
__device__ float g_bufY[BUF_ELEMS];   // attention out row-major [B,T,N,F] (tf32)
__device__ float g_PH[BUF_ELEMS];     // packed tf32(xh+te), 64x32 fragment tiles
__device__ float g_PHH[BUF_ELEMS];    // packed relu(ff1)
__device__ float g_bufW[6 * 256 * 256];  // packed tf32 weight fragments

// ---------------- tf32 + async-copy helpers ----------------
DINL uint32_t f2tf(float x) {
    uint32_t r;
    asm("cvt.rna.tf32.f32 %0, %1;" : "=r"(r) : "f"(x));
    return r;
}
DINL float tf2f(float x) { return __uint_as_float(f2tf(x)); }

DINL void mma8(float* c, const uint32_t* a, const uint32_t* b) {
    asm volatile(
        "mma.sync.aligned.m16n8k8.row.col.f32.tf32.tf32.f32 "
        "{%0,%1,%2,%3}, {%4,%5,%6,%7}, {%8,%9}, {%0,%1,%2,%3};"
        : "+f"(c[0]), "+f"(c[1]), "+f"(c[2]), "+f"(c[3])
        : "r"(a[0]), "r"(a[1]), "r"(a[2]), "r"(a[3]), "r"(b[0]), "r"(b[1]));
}

DINL void cpa16(float* smem_dst, const float* gsrc) {
    uint32_t d = (uint32_t)__cvta_generic_to_shared(smem_dst);
    asm volatile("cp.async.cg.shared.global [%0], [%1], 16;\n" :: "r"(d), "l"(gsrc));
}
#define CP_COMMIT()  asm volatile("cp.async.commit_group;\n")
#define CP_WAIT(n)   asm volatile("cp.async.wait_group %0;\n" :: "n"(n))

// packed-tile inner offset for (mrow in [0,64), kc32 in [0,32))
DINL int pk_off(int mrow, int kc32) {
    int mi = mrow >> 4, r = mrow & 15, kii = kc32 >> 3, kc = kc32 & 7;
    return ((mi * 4 + kii) * 32 + (r & 7) * 4 + (kc & 3)) * 4 + (r >> 3) + ((kc >> 2) << 1);
}

// =====================================================================
// Pre-pass: bufX = tf32(xl+te) row-major;  PH = packed tf32(xh+te)
// grid 4800, 256 thr, 64 rows per CTA, 8 k-slices.
// =====================================================================
__global__ __launch_bounds__(256) void prep_x(
    const float* __restrict__ xl, const float* __restrict__ xh,
    const float* __restrict__ te)
{
    __shared__ float sH[2048];
    const int mt = blockIdx.x, m0 = mt * 64, tid = threadIdx.x;
    for (int ks = 0; ks < 8; ks++) {
#pragma unroll
        for (int j = 0; j < 2; j++) {
            int cc = j * 256 + tid;          // 0..511
            int r = cc >> 3, c4 = cc & 7;
            int m = m0 + r;
            long g = (long)m * 256 + ks * 32 + c4 * 4;
            int bt = m / Nn;
            float4 t4 = *(const float4*)(te + bt * 256 + ks * 32 + c4 * 4);
            float4 a = *(const float4*)(xl + g);
            float4 b = *(const float4*)(xh + g);
            a.x = tf2f(a.x + t4.x); a.y = tf2f(a.y + t4.y);
            a.z = tf2f(a.z + t4.z); a.w = tf2f(a.w + t4.w);
            b.x += t4.x; b.y += t4.y; b.z += t4.z; b.w += t4.w;
            *(float4*)(g_bufX + g) = a;
            int k0 = c4 * 4;
            sH[pk_off(r, k0 + 0)] = tf2f(b.x); sH[pk_off(r, k0 + 1)] = tf2f(b.y);
            sH[pk_off(r, k0 + 2)] = tf2f(b.z); sH[pk_off(r, k0 + 3)] = tf2f(b.w);
        }
        __syncthreads();
        long base = ((long)mt * 8 + ks) * 2048;
#pragma unroll
        for (int j = 0; j < 2; j++) {
            int idx = j * 256 + tid;
            *(float4*)(g_PH + base + idx * 4) = *(const float4*)(sH + idx * 4);
        }
        __syncthreads();
    }
}

// =====================================================================
// Pack all 6 weights [256x256] (W[n][k]) into B fragment layout.
// =====================================================================
__global__ __launch_bounds__(256) void pack_w6(
    const float* __restrict__ W0, const float* __restrict__ W1,
    const float* __restrict__ W2, const float* __restrict__ W3,
    const float* __restrict__ W4, const float* __restrict__ W5)
{
    int widx = blockIdx.x >> 8;
    const float* W;
    switch (widx) {
        case 0: W = W0; break;
        case 1: W = W1; break;
        case 2: W = W2; break;
        case 3: W = W3; break;
        case 4: W = W4; break;
        default: W = W5; break;
    }
    int i = (blockIdx.x & 255) * 256 + threadIdx.x;  // 0..65535
    int n = i >> 8, k = i & 255;
    int kb = k >> 3, nb = n >> 3;
    int lanei = (n & 7) * 4 + (k & 3);
    int reg = (k >> 2) & 1;
    g_bufW[widx * 65536 + ((kb * 32 + nb) * 32 + lanei) * 2 + reg] = tf2f(W[i]);
}

// =====================================================================
// GEMM v8 (packed A): BM=128, BN=256, BK=32. 512 thr = 16 warps (2m x 8n),
// warp tile 64x32 (64 accum regs). grid 2400.
// =====================================================================
constexpr int A2_TILE = 4096;                    // 2 packed m-tiles x 32k
constexpr int B2_TILE = 8192;                    // 32k x 256n packed W slice
constexpr int GEMM_SMEM_P = (2 * B2_TILE + 2 * A2_TILE) * 4;   // 98304

__global__ __launch_bounds__(512, 1) void gemm_p(
    const float* __restrict__ Apk, const float* __restrict__ Wp,
    const float* __restrict__ bias, const float* __restrict__ R,
    float* __restrict__ Ofp,
    int relu, int trans, int docvt)
{
    extern __shared__ float sm[];
    float* Bs = sm;                      // 2 x 8192
    float* As = sm + 2 * B2_TILE;        // 2 x 4096

    const int tid = threadIdx.x;
    const int lane = tid & 31, wid = tid >> 5;
    const int wm = wid & 1;                      // 2 m-warps (64 rows each)
    const int wn = wid >> 1;                     // 8 n-warps (32 cols each)
    const int bx = blockIdx.x;
    const int m0 = bx * 128;
    const float* Abase = Apk + (long)bx * 32768;

    auto stage = [&](int kt, int b) {
        float* adst = As + b * A2_TILE;
        cpa16(adst + tid * 4, Abase + kt * 2048 + tid * 4);                 // m-tile 0
        cpa16(adst + 2048 + tid * 4, Abase + 16384 + kt * 2048 + tid * 4);  // m-tile 1
        const float* bsrc = Wp + kt * 8192;
        float* bdst = Bs + b * B2_TILE;
#pragma unroll
        for (int j = 0; j < 4; j++) {
            int c = j * 512 + tid;
            cpa16(bdst + c * 4, bsrc + c * 4);
        }
        CP_COMMIT();
    };

    float c[4][4][4];
#pragma unroll
    for (int i = 0; i < 4; i++)
#pragma unroll
        for (int j = 0; j < 4; j++)
#pragma unroll
            for (int k2 = 0; k2 < 4; k2++) c[i][j][k2] = 0.f;

    stage(0, 0);

    for (int kt = 0; kt < 8; kt++) {
        if (kt < 7) stage(kt + 1, (kt + 1) & 1);
        if (kt < 7) { CP_WAIT(1); } else { CP_WAIT(0); }
        __syncthreads();

        const float* Ab = As + (kt & 1) * A2_TILE + wm * 2048;
        const float* Bb = Bs + (kt & 1) * B2_TILE;
#pragma unroll
        for (int ks = 0; ks < 4; ks++) {
            uint32_t a[4][4];
#pragma unroll
            for (int im = 0; im < 4; im++) {
                float4 av = *(const float4*)(Ab + ((im * 4 + ks) * 32 + lane) * 4);
                a[im][0] = __float_as_uint(av.x); a[im][1] = __float_as_uint(av.y);
                a[im][2] = __float_as_uint(av.z); a[im][3] = __float_as_uint(av.w);
            }
#pragma unroll
            for (int in = 0; in < 4; in++) {
                const float2 bv = *(const float2*)&Bb[((ks * 32 + wn * 4 + in) * 32 + lane) * 2];
                uint32_t b[2] = { __float_as_uint(bv.x), __float_as_uint(bv.y) };
#pragma unroll
                for (int im = 0; im < 4; im++) mma8(c[im][in], a[im], b);
            }
        }
        __syncthreads();
    }

#pragma unroll
    for (int im = 0; im < 4; im++) {
#pragma unroll
        for (int h = 0; h < 2; h++) {
            int row = m0 + wm * 64 + im * 16 + (lane >> 2) + h * 8;
            long ob;
            if (trans) {
                int bt = row / Nn;
                int nidx = row - bt * Nn;
                int t = bt % Tt, bbi = bt / Tt;
                ob = ((long)(bbi * Nn + nidx) * Tt + t) * 256;
            } else {
                ob = (long)row * 256;
            }
#pragma unroll
            for (int in = 0; in < 4; in++) {
                int col = wn * 32 + in * 8 + (lane & 3) * 2;
                float v0 = c[im][in][h * 2 + 0] + bias[col];
                float v1 = c[im][in][h * 2 + 1] + bias[col + 1];
                if (R) {
                    v0 += R[(long)row * 256 + col];
                    v1 += R[(long)row * 256 + col + 1];
                }
                if (relu) { v0 = fmaxf(v0, 0.f); v1 = fmaxf(v1, 0.f); }
                if (docvt) { v0 = tf2f(v0); v1 = tf2f(v1); }
                *(float2*)(Ofp + ob + col) = make_float2(v0, v1);
            }
        }
    }
}

// =====================================================================
// GEMM v8 (row-major A): same shape; optional packed output (smem-staged).
// =====================================================================
constexpr int AR_STRIDE = 36;
constexpr int AR_TILE = 128 * AR_STRIDE;         // 4608
constexpr int GEMM_SMEM_R = (2 * B2_TILE + 2 * AR_TILE) * 4;  // 104448

__global__ __launch_bounds__(512, 1) void gemm_r(
    const float* __restrict__ Arow, const float* __restrict__ Wp,
    const float* __restrict__ bias, const float* __restrict__ R,
    float* __restrict__ Ofp, float* __restrict__ Opk,
    int relu, int trans, int docvt)
{
    extern __shared__ float sm[];
    float* Bs = sm;                      // 2 x 8192
    float* As = sm + 2 * B2_TILE;        // 2 x 4608

    const int tid = threadIdx.x;
    const int lane = tid & 31, wid = tid >> 5;
    const int wm = wid & 1;
    const int wn = wid >> 1;
    const int bx = blockIdx.x;
    const int m0 = bx * 128;

    auto stage = [&](int kt, int b) {
        const float* asrc = Arow + (long)m0 * 256 + kt * 32;
        float* adst = As + b * AR_TILE;
#pragma unroll
        for (int j = 0; j < 2; j++) {
            int cc = j * 512 + tid;              // 0..1023
            int row = cc >> 3, c4 = cc & 7;
            cpa16(adst + row * AR_STRIDE + c4 * 4, asrc + (long)row * 256 + c4 * 4);
        }
        const float* bsrc = Wp + kt * 8192;
        float* bdst = Bs + b * B2_TILE;
#pragma unroll
        for (int j = 0; j < 4; j++) {
            int c = j * 512 + tid;
            cpa16(bdst + c * 4, bsrc + c * 4);
        }
        CP_COMMIT();
    };

    float c[4][4][4];
#pragma unroll
    for (int i = 0; i < 4; i++)
#pragma unroll
        for (int j = 0; j < 4; j++)
#pragma unroll
            for (int k2 = 0; k2 < 4; k2++) c[i][j][k2] = 0.f;

    stage(0, 0);

    for (int kt = 0; kt < 8; kt++) {
        if (kt < 7) stage(kt + 1, (kt + 1) & 1);
        if (kt < 7) { CP_WAIT(1); } else { CP_WAIT(0); }
        __syncthreads();

        const float* Ab = As + (kt & 1) * AR_TILE;
        const float* Bb = Bs + (kt & 1) * B2_TILE;
#pragma unroll
        for (int ks = 0; ks < 4; ks++) {
            uint32_t a[4][4];
#pragma unroll
            for (int im = 0; im < 4; im++) {
                const float* ap = Ab + (wm * 64 + im * 16 + (lane >> 2)) * AR_STRIDE
                                     + ks * 8 + (lane & 3);
                a[im][0] = __float_as_uint(ap[0]);
                a[im][1] = __float_as_uint(ap[8 * AR_STRIDE]);
                a[im][2] = __float_as_uint(ap[4]);
                a[im][3] = __float_as_uint(ap[8 * AR_STRIDE + 4]);
            }
#pragma unroll
            for (int in = 0; in < 4; in++) {
                const float2 bv = *(const float2*)&Bb[((ks * 32 + wn * 4 + in) * 32 + lane) * 2];
                uint32_t b[2] = { __float_as_uint(bv.x), __float_as_uint(bv.y) };
#pragma unroll
                for (int im = 0; im < 4; im++) mma8(c[im][in], a[im], b);
            }
        }
        __syncthreads();
    }

    if (Ofp) {
#pragma unroll
        for (int im = 0; im < 4; im++) {
#pragma unroll
            for (int h = 0; h < 2; h++) {
                int row = m0 + wm * 64 + im * 16 + (lane >> 2) + h * 8;
                long ob;
                if (trans) {
                    int bt = row / Nn;
                    int nidx = row - bt * Nn;
                    int t = bt % Tt, bbi = bt / Tt;
                    ob = ((long)(bbi * Nn + nidx) * Tt + t) * 256;
                } else {
                    ob = (long)row * 256;
                }
#pragma unroll
                for (int in = 0; in < 4; in++) {
                    int col = wn * 32 + in * 8 + (lane & 3) * 2;
                    float v0 = c[im][in][h * 2 + 0] + bias[col];
                    float v1 = c[im][in][h * 2 + 1] + bias[col + 1];
                    if (R) {
                        v0 += R[(long)row * 256 + col];
                        v1 += R[(long)row * 256 + col + 1];
                    }
                    if (relu) { v0 = fmaxf(v0, 0.f); v1 = fmaxf(v1, 0.f); }
                    if (docvt) { v0 = tf2f(v0); v1 = tf2f(v1); }
                    *(float2*)(Ofp + ob + col) = make_float2(v0, v1);
                }
            }
        }
    }
    if (Opk) {   // packed output: two phases, each 64 rows staged + flushed
#pragma unroll
        for (int p = 0; p < 2; p++) {
            __syncthreads();
            if (wm == p) {
#pragma unroll
                for (int im = 0; im < 4; im++)
#pragma unroll
                    for (int h = 0; h < 2; h++) {
                        int mrow = im * 16 + (lane >> 2) + h * 8;   // 0..63
#pragma unroll
                        for (int in = 0; in < 4; in++) {
                            int col = wn * 32 + in * 8 + (lane & 3) * 2;
                            float v0 = c[im][in][h * 2 + 0] + bias[col];
                            float v1 = c[im][in][h * 2 + 1] + bias[col + 1];
                            if (relu) { v0 = fmaxf(v0, 0.f); v1 = fmaxf(v1, 0.f); }
                            int off = (col >> 5) * 2048 + pk_off(mrow, col & 31);
                            sm[off]     = tf2f(v0);
                            sm[off + 4] = tf2f(v1);
                        }
                    }
            }
            __syncthreads();
            long base = (long)(bx * 2 + p) * 16384;
#pragma unroll
            for (int j = 0; j < 8; j++) {
                int idx = j * 512 + tid;         // float4 idx 0..4095
                *(float4*)(Opk + base + idx * 4) = *(const float4*)(sm + idx * 4);
            }
        }
    }
}

// =====================================================================
// Fused attention: S=q@k^T in smem, masked softmax, O=P@V -> bufY row-major
// =====================================================================
constexpr int S_STRIDE = 100;
constexpr int ATTN_SMEM = (96 * S_STRIDE + 6144) * 4;  // 62976 B

__global__ __launch_bounds__(256) void attn_fused() {
    extern __shared__ float sm[];
    float* S = sm;
    float* As = sm + 96 * S_STRIDE;
    float* Bs = As + 3072;
    float* Vs = As;

    const int head = blockIdx.x;
    const int tid = threadIdx.x, lane = tid & 31, wid = tid >> 5;
    const int wm = wid & 1, wn = wid >> 1;
    const float* qh = g_bufA + (long)head * (Tt * 256);
    const float* kh = g_bufB + (long)head * (Tt * 256);
    const float* vh = g_bufC + (long)head * (Tt * 256);

    {
        float c[3][3][4] = {};
        for (int kt = 0; kt < 256; kt += 32) {
#pragma unroll
            for (int j = 0; j < 3; j++) {
                int idx = j * 256 + tid;
                int ar = idx >> 3, ac4 = idx & 7;
                float4 v = *(const float4*)(qh + ar * 256 + kt + ac4 * 4);
                int mi = ar >> 4, r = ar & 15;
                int kii = ac4 >> 1, regb = (r >> 3) + ((ac4 & 1) << 1);
                float* dst = &As[((mi * 4 + kii) * 32 + (r & 7) * 4) * 4 + regb];
                dst[0] = v.x; dst[4] = v.y; dst[8] = v.z; dst[12] = v.w;
            }
#pragma unroll
            for (int j = 0; j < 3; j++) {
                int idx = j * 256 + tid;
                int br = idx >> 3, bc4 = idx & 7;
                float4 v = *(const float4*)(kh + br * 256 + kt + bc4 * 4);
                int ni = br >> 3, nr = br & 7;
                int kii = bc4 >> 1, regb = bc4 & 1;
                float* dst = &Bs[((ni * 4 + kii) * 32 + nr * 4) * 2 + regb];
                dst[0] = v.x; dst[2] = v.y; dst[4] = v.z; dst[6] = v.w;
            }
            __syncthreads();
#pragma unroll
            for (int ks = 0; ks < 4; ks++) {
                uint32_t a[3][4], b[3][2];
#pragma unroll
                for (int im = 0; im < 3; im++) {
                    float4 av = *(const float4*)&As[(((wm * 3 + im) * 4 + ks) * 32 + lane) * 4];
                    a[im][0] = __float_as_uint(av.x); a[im][1] = __float_as_uint(av.y);
                    a[im][2] = __float_as_uint(av.z); a[im][3] = __float_as_uint(av.w);
                }
#pragma unroll
                for (int in = 0; in < 3; in++) {
                    float2 bv = *(const float2*)&Bs[(((wn * 3 + in) * 4 + ks) * 32 + lane) * 2];
                    b[in][0] = __float_as_uint(bv.x); b[in][1] = __float_as_uint(bv.y);
                }
#pragma unroll
                for (int im = 0; im < 3; im++)
#pragma unroll
                    for (int in = 0; in < 3; in++)
                        mma8(c[im][in], a[im], b[in]);
            }
            __syncthreads();
        }
#pragma unroll
        for (int im = 0; im < 3; im++)
#pragma unroll
            for (int h = 0; h < 2; h++) {
                int row = wm * 48 + im * 16 + (lane >> 2) + h * 8;
#pragma unroll
                for (int in = 0; in < 3; in++) {
                    int col = wn * 24 + in * 8 + (lane & 3) * 2;
                    *(float2*)(S + row * S_STRIDE + col) =
                        make_float2(c[im][in][h * 2], c[im][in][h * 2 + 1]);
                }
            }
    }
    __syncthreads();

#pragma unroll
    for (int r = 0; r < 12; r++) {
        int row = wid * 12 + r;
        float* p = S + row * S_STRIDE;
        float x[3];
#pragma unroll
        for (int j = 0; j < 3; j++) {
            int col = lane + j * 32;
            float s = p[col];
            x[j] = (col <= row) ? s * 0.0625f : (-32767.0f * 0.0625f);
        }
        float mx = fmaxf(x[0], fmaxf(x[1], x[2]));
#pragma unroll
        for (int o = 16; o > 0; o >>= 1) mx = fmaxf(mx, __shfl_xor_sync(0xffffffffu, mx, o));
        float e0 = __expf(x[0] - mx), e1 = __expf(x[1] - mx), e2 = __expf(x[2] - mx);
        float sum = e0 + e1 + e2;
#pragma unroll
        for (int o = 16; o > 0; o >>= 1) sum += __shfl_xor_sync(0xffffffffu, sum, o);
        float inv = 1.0f / sum;
        p[lane]      = tf2f(e0 * inv);
        p[lane + 32] = tf2f(e1 * inv);
        p[lane + 64] = tf2f(e2 * inv);
    }
    __syncthreads();

    const int bbi = head / Nn, nh = head % Nn;
    for (int n0 = 0; n0 < 256; n0 += 64) {
#pragma unroll
        for (int j = 0; j < 6; j++) {
            int idx = j * 256 + tid;
            int sr = idx >> 4, f4 = idx & 15;
            float4 vv = *(const float4*)(vh + sr * 256 + n0 + f4 * 4);
            int kt = sr >> 5, srl = sr & 31;
            int ni = f4 >> 1;
            int kii = srl >> 3;
            int regb = (srl >> 2) & 1;
            int lb = (f4 & 1) * 16 + (srl & 3);
            float* dst = &Vs[kt * 2048 + ((ni * 4 + kii) * 32) * 2 + regb];
            dst[(lb + 0) * 2]  = vv.x;
            dst[(lb + 4) * 2]  = vv.y;
            dst[(lb + 8) * 2]  = vv.z;
            dst[(lb + 12) * 2] = vv.w;
        }
        __syncthreads();

        float c[3][2][4] = {};
#pragma unroll
        for (int kt = 0; kt < 3; kt++) {
#pragma unroll
            for (int ks = 0; ks < 4; ks++) {
                uint32_t a[3][4], b[2][2];
#pragma unroll
                for (int im = 0; im < 3; im++) {
                    const float* ap = S + (wm * 48 + im * 16 + (lane >> 2)) * S_STRIDE
                                        + kt * 32 + ks * 8 + (lane & 3);
                    a[im][0] = __float_as_uint(ap[0]);
                    a[im][1] = __float_as_uint(ap[8 * S_STRIDE]);
                    a[im][2] = __float_as_uint(ap[4]);
                    a[im][3] = __float_as_uint(ap[8 * S_STRIDE + 4]);
                }
#pragma unroll
                for (int in = 0; in < 2; in++) {
                    float2 bv = *(const float2*)&Vs[kt * 2048 +
                        (((wn * 2 + in) * 4 + ks) * 32 + lane) * 2];
                    b[in][0] = __float_as_uint(bv.x); b[in][1] = __float_as_uint(bv.y);
                }
#pragma unroll
                for (int im = 0; im < 3; im++)
#pragma unroll
                    for (int in = 0; in < 2; in++)
                        mma8(c[im][in], a[im], b[in]);
            }
        }
#pragma unroll
        for (int im = 0; im < 3; im++)
#pragma unroll
            for (int h = 0; h < 2; h++) {
                int t = wm * 48 + im * 16 + (lane >> 2) + h * 8;
                long ob = ((long)(bbi * Tt + t) * Nn + nh) * 256;
#pragma unroll
                for (int in = 0; in < 2; in++) {
                    int f = n0 + wn * 16 + in * 8 + (lane & 3) * 2;
                    *(float2*)(g_bufY + ob + f) =
                        make_float2(tf2f(c[im][in][h * 2]), tf2f(c[im][in][h * 2 + 1]));
                }
            }
        __syncthreads();
    }
}

// =====================================================================
// LayerNorm over F=256. One warp per row. Optional tf32-rounded output.
// =====================================================================
__global__ __launch_bounds__(256) void ln_k(
    const float* __restrict__ in, float* __restrict__ outfp, int docvt)
{
    long row = (long)blockIdx.x * 8 + (threadIdx.x >> 5);
    int lane = threadIdx.x & 31;
    const float* p = in + row * 256;
    float4 a = *(const float4*)(p + lane * 4);
    float4 b = *(const float4*)(p + 128 + lane * 4);
    float s = a.x + a.y + a.z + a.w + b.x + b.y + b.z + b.w;
    float q = a.x * a.x + a.y * a.y + a.z * a.z + a.w * a.w +
              b.x * b.x + b.y * b.y + b.z * b.z + b.w * b.w;
#pragma unroll
    for (int o = 16; o > 0; o >>= 1) {
        s += __shfl_xor_sync(0xffffffffu, s, o);
        q += __shfl_xor_sync(0xffffffffu, q, o);
    }
    float mean = s * (1.0f / 256.0f);
    float var = q * (1.0f / 256.0f) - mean * mean;
    float rs = rsqrtf(var + 1e-5f);
    float4 oa = make_float4((a.x - mean) * rs, (a.y - mean) * rs,
                            (a.z - mean) * rs, (a.w - mean) * rs);
    float4 ob = make_float4((b.x - mean) * rs, (b.y - mean) * rs,
                            (b.z - mean) * rs, (b.w - mean) * rs);
    if (docvt) {
        oa.x = tf2f(oa.x); oa.y = tf2f(oa.y); oa.z = tf2f(oa.z); oa.w = tf2f(oa.w);
        ob.x = tf2f(ob.x); ob.y = tf2f(ob.y); ob.z = tf2f(ob.z); ob.w = tf2f(ob.w);
    }
    float* op = outfp + row * 256;
    *(float4*)(op + lane * 4) = oa;
    *(float4*)(op + 128 + lane * 4) = ob;
}

// =====================================================================
extern "C" void kernel_launch(void* const* d_in, const int* in_sizes, int n_in,
                              void* d_out, int out_size) {
    const float* xl  = (const float*)d_in[0];
    const float* xh  = (const float*)d_in[1];
    const float* te  = (const float*)d_in[2];
    const float* Wq  = (const float*)d_in[3];
    const float* bq  = (const float*)d_in[4];
    const float* Wk  = (const float*)d_in[5];
    const float* bk  = (const float*)d_in[6];
    const float* Wv  = (const float*)d_in[7];
    const float* bv  = (const float*)d_in[8];
    const float* Wo  = (const float*)d_in[9];
    const float* bo  = (const float*)d_in[10];
    const float* Wf1 = (const float*)d_in[11];
    const float* bf1 = (const float*)d_in[12];
    const float* Wf2 = (const float*)d_in[13];
    const float* bf2 = (const float*)d_in[14];
    float* out = (float*)d_out;

    static bool init = false;
    static float *wbase, *bA, *bB, *bC, *bX, *bY, *pH, *pHH;
    if (!init) {
        cudaFuncSetAttribute(gemm_p, cudaFuncAttributeMaxDynamicSharedMemorySize, GEMM_SMEM_P);
        cudaFuncSetAttribute(gemm_r, cudaFuncAttributeMaxDynamicSharedMemorySize, GEMM_SMEM_R);
        cudaFuncSetAttribute(attn_fused, cudaFuncAttributeMaxDynamicSharedMemorySize, ATTN_SMEM);
        cudaGetSymbolAddress((void**)&wbase, g_bufW);
        cudaGetSymbolAddress((void**)&bA, g_bufA);
        cudaGetSymbolAddress((void**)&bB, g_bufB);
        cudaGetSymbolAddress((void**)&bC, g_bufC);
        cudaGetSymbolAddress((void**)&bX, g_bufX);
        cudaGetSymbolAddress((void**)&bY, g_bufY);
        cudaGetSymbolAddress((void**)&pH, g_PH);
        cudaGetSymbolAddress((void**)&pHH, g_PHH);
        init = true;
    }

    prep_x<<<Mtot / 64, 256>>>(xl, xh, te);
    pack_w6<<<1536, 256>>>(Wq, Wk, Wv, Wo, Wf1, Wf2);

    dim3 gg(Mtot / 128);   // 2400 CTAs per dense GEMM

    // q = X @ Wq^T + bq            -> bufA [B,N,T,F], tf32-rounded
    gemm_r<<<gg, 512, GEMM_SMEM_R>>>(bX, wbase + 0 * 65536, bq, nullptr, bA, nullptr, 0, 1, 1);
    // k = relu(H @ Wk^T + bk)      -> bufB [B,N,T,F]
    gemm_p<<<gg, 512, GEMM_SMEM_P>>>(pH, wbase + 1 * 65536, bk, nullptr, bB, 1, 1, 1);
    // v = relu(H @ Wv^T + bv)      -> bufC [B,N,T,F]
    gemm_p<<<gg, 512, GEMM_SMEM_P>>>(pH, wbase + 2 * 65536, bv, nullptr, bC, 1, 1, 1);

    attn_fused<<<HEADS, 256, ATTN_SMEM>>>();       // -> bufY row-major (tf32)

    // preLN1 = Y @ Wo^T + bo + X   -> bufA fp32 row-major
    gemm_r<<<gg, 512, GEMM_SMEM_R>>>(bY, wbase + 3 * 65536, bo, bX, bA, nullptr, 0, 0, 0);
    // out1 = LN(preLN1), tf32-rounded, in place
    ln_k<<<Mtot / 8, 256>>>(bA, bA, 1);

    // h = relu(out1 @ Wf1^T + bf1) -> pHH packed only
    gemm_r<<<gg, 512, GEMM_SMEM_R>>>(bA, wbase + 4 * 65536, bf1, nullptr, nullptr, pHH, 1, 0, 1);
    // preLN2 = h @ Wf2^T + bf2 + out1 -> bufB fp32
    gemm_p<<<gg, 512, GEMM_SMEM_P>>>(pHH, wbase + 5 * 65536, bf2, bA, bB, 0, 0, 0);
    ln_k<<<Mtot / 8, 256>>>(bB, out, 0);           // final LN -> d_out
}

// round 16
// speedup vs baseline: 1.0537x; 1.0473x over previous
#include <cuda_runtime.h>
#include <cstdint>

#define DINL __device__ __forceinline__

constexpr int Tt = 96, Nn = 400, Fd = 256;
constexpr int Bb = 8;
constexpr int Mtot = Bb * Tt * Nn;              // 307200
constexpr int HEADS = Bb * Nn;                  // 3200
constexpr long BUF_ELEMS = (long)Mtot * Fd;     // 78,643,200

// ---------------- scratch (device globals; no allocation APIs) ----------------
__device__ float g_bufA[BUF_ELEMS];   // q [B,N,T,F] -> preLN1 -> out1 fp32
__device__ float g_bufB[BUF_ELEMS];   // k [B,N,T,F] -> preLN2 fp32
__device__ float g_bufC[BUF_ELEMS];   // v [B,N,T,F]
__device__ float g_bufX[BUF_ELEMS];   // tf32(xl + te) row-major (residual + q-GEMM A)
__device__ float g_bufY[BUF_ELEMS];   // attention out row-major [B,T,N,F] (tf32)
__device__ float g_PH[BUF_ELEMS];     // packed tf32(xh+te), 64x32 fragment tiles
__device__ float g_PHH[BUF_ELEMS];    // packed relu(ff1)
__device__ float g_bufW[6 * 256 * 256];  // packed tf32 weight fragments

// ---------------- tf32 + async-copy helpers ----------------
DINL uint32_t f2tf(float x) {
    uint32_t r;
    asm("cvt.rna.tf32.f32 %0, %1;" : "=r"(r) : "f"(x));
    return r;
}
DINL float tf2f(float x) { return __uint_as_float(f2tf(x)); }

DINL void mma8(float* c, const uint32_t* a, const uint32_t* b) {
    asm volatile(
        "mma.sync.aligned.m16n8k8.row.col.f32.tf32.tf32.f32 "
        "{%0,%1,%2,%3}, {%4,%5,%6,%7}, {%8,%9}, {%0,%1,%2,%3};"
        : "+f"(c[0]), "+f"(c[1]), "+f"(c[2]), "+f"(c[3])
        : "r"(a[0]), "r"(a[1]), "r"(a[2]), "r"(a[3]), "r"(b[0]), "r"(b[1]));
}

DINL void cpa16(float* smem_dst, const float* gsrc) {
    uint32_t d = (uint32_t)__cvta_generic_to_shared(smem_dst);
    asm volatile("cp.async.cg.shared.global [%0], [%1], 16;\n" :: "r"(d), "l"(gsrc));
}
#define CP_COMMIT()  asm volatile("cp.async.commit_group;\n")
#define CP_WAIT(n)   asm volatile("cp.async.wait_group %0;\n" :: "n"(n))

// packed-tile inner offset for (mrow in [0,64), kc32 in [0,32))
DINL int pk_off(int mrow, int kc32) {
    int mi = mrow >> 4, r = mrow & 15, kii = kc32 >> 3, kc = kc32 & 7;
    return ((mi * 4 + kii) * 32 + (r & 7) * 4 + (kc & 3)) * 4 + (r >> 3) + ((kc >> 2) << 1);
}

// =====================================================================
// Pre-pass: bufX = tf32(xl+te) row-major;  PH = packed tf32(xh+te)
// =====================================================================
__global__ __launch_bounds__(256) void prep_x(
    const float* __restrict__ xl, const float* __restrict__ xh,
    const float* __restrict__ te)
{
    __shared__ float sH[2048];
    const int mt = blockIdx.x, m0 = mt * 64, tid = threadIdx.x;
    for (int ks = 0; ks < 8; ks++) {
#pragma unroll
        for (int j = 0; j < 2; j++) {
            int cc = j * 256 + tid;          // 0..511
            int r = cc >> 3, c4 = cc & 7;
            int m = m0 + r;
            long g = (long)m * 256 + ks * 32 + c4 * 4;
            int bt = m / Nn;
            float4 t4 = *(const float4*)(te + bt * 256 + ks * 32 + c4 * 4);
            float4 a = *(const float4*)(xl + g);
            float4 b = *(const float4*)(xh + g);
            a.x = tf2f(a.x + t4.x); a.y = tf2f(a.y + t4.y);
            a.z = tf2f(a.z + t4.z); a.w = tf2f(a.w + t4.w);
            b.x += t4.x; b.y += t4.y; b.z += t4.z; b.w += t4.w;
            *(float4*)(g_bufX + g) = a;
            int k0 = c4 * 4;
            sH[pk_off(r, k0 + 0)] = tf2f(b.x); sH[pk_off(r, k0 + 1)] = tf2f(b.y);
            sH[pk_off(r, k0 + 2)] = tf2f(b.z); sH[pk_off(r, k0 + 3)] = tf2f(b.w);
        }
        __syncthreads();
        long base = ((long)mt * 8 + ks) * 2048;
#pragma unroll
        for (int j = 0; j < 2; j++) {
            int idx = j * 256 + tid;
            *(float4*)(g_PH + base + idx * 4) = *(const float4*)(sH + idx * 4);
        }
        __syncthreads();
    }
}

// =====================================================================
// Pack all 6 weights [256x256] (W[n][k]) into B fragment layout.
// =====================================================================
__global__ __launch_bounds__(256) void pack_w6(
    const float* __restrict__ W0, const float* __restrict__ W1,
    const float* __restrict__ W2, const float* __restrict__ W3,
    const float* __restrict__ W4, const float* __restrict__ W5)
{
    int widx = blockIdx.x >> 8;
    const float* W;
    switch (widx) {
        case 0: W = W0; break;
        case 1: W = W1; break;
        case 2: W = W2; break;
        case 3: W = W3; break;
        case 4: W = W4; break;
        default: W = W5; break;
    }
    int i = (blockIdx.x & 255) * 256 + threadIdx.x;  // 0..65535
    int n = i >> 8, k = i & 255;
    int kb = k >> 3, nb = n >> 3;
    int lanei = (n & 7) * 4 + (k & 3);
    int reg = (k >> 2) & 1;
    g_bufW[widx * 65536 + ((kb * 32 + nb) * 32 + lanei) * 2 + reg] = tf2f(W[i]);
}

// =====================================================================
// GEMM packed-A (R12 config): BM=64, BN=128, BK=32; 256 thr (2m x 4n);
// grid (4800, 2); 3 CTAs/SM.
// =====================================================================
constexpr int A_TILE = 2048;
constexpr int B_TILE = 4096;
constexpr int GEMM_SMEM_P = (2 * B_TILE + 2 * A_TILE) * 4;   // 49152

__global__ __launch_bounds__(256, 3) void gemm_p(
    const float* __restrict__ Apk, const float* __restrict__ Wp,
    const float* __restrict__ bias, const float* __restrict__ R,
    float* __restrict__ Ofp,
    int relu, int trans, int docvt)
{
    extern __shared__ float sm[];
    float* Bs = sm;                      // 2 x 4096
    float* As = sm + 2 * B_TILE;         // 2 x 2048

    const int tid = threadIdx.x;
    const int lane = tid & 31, wid = tid >> 5;
    const int wmm = wid & 1;
    const int wnn = (wid >> 1) & 3;
    const int m0 = blockIdx.x * 64;
    const int nhalf = blockIdx.y;
    const int nb_off = nhalf * 1024;
    const float* Abase = Apk + (long)blockIdx.x * 16384;

    auto stage = [&](int kt, int b) {
        const float* asrc = Abase + kt * 2048;
        float* adst = As + b * A_TILE;
#pragma unroll
        for (int j = 0; j < 2; j++) {
            int c = j * 256 + tid;
            cpa16(adst + c * 4, asrc + c * 4);
        }
        const float* bsrc = Wp + kt * 8192 + nb_off;
        float* bdst = Bs + b * B_TILE;
#pragma unroll
        for (int j = 0; j < 4; j++) {
            int c = j * 256 + tid;
            int chunk = c >> 8, within = c & 255;
            cpa16(bdst + chunk * 1024 + within * 4, bsrc + chunk * 2048 + within * 4);
        }
        CP_COMMIT();
    };

    float c[2][4][4];
#pragma unroll
    for (int i = 0; i < 2; i++)
#pragma unroll
        for (int j = 0; j < 4; j++)
#pragma unroll
            for (int k2 = 0; k2 < 4; k2++) c[i][j][k2] = 0.f;

    stage(0, 0);

    for (int kt = 0; kt < 8; kt++) {
        if (kt < 7) stage(kt + 1, (kt + 1) & 1);
        if (kt < 7) { CP_WAIT(1); } else { CP_WAIT(0); }
        __syncthreads();

        const float* Ab = As + (kt & 1) * A_TILE;
        const float* Bb = Bs + (kt & 1) * B_TILE;
#pragma unroll
        for (int ks = 0; ks < 4; ks++) {
            uint32_t a[2][4];
#pragma unroll
            for (int im = 0; im < 2; im++) {
                float4 av = *(const float4*)(Ab + ((wmm * 2 + im) * 4 + ks) * 128 + lane * 4);
                a[im][0] = __float_as_uint(av.x); a[im][1] = __float_as_uint(av.y);
                a[im][2] = __float_as_uint(av.z); a[im][3] = __float_as_uint(av.w);
            }
#pragma unroll
            for (int in = 0; in < 4; in++) {
                const float2 bv = *(const float2*)&Bb[ks * 1024 + (wnn * 4 + in) * 64 + lane * 2];
                uint32_t b[2] = { __float_as_uint(bv.x), __float_as_uint(bv.y) };
#pragma unroll
                for (int im = 0; im < 2; im++) mma8(c[im][in], a[im], b);
            }
        }
        __syncthreads();
    }

#pragma unroll
    for (int im = 0; im < 2; im++) {
#pragma unroll
        for (int h = 0; h < 2; h++) {
            int row = m0 + wmm * 32 + im * 16 + (lane >> 2) + h * 8;
            long ob;
            if (trans) {
                int bt = row / Nn;
                int nidx = row - bt * Nn;
                int t = bt % Tt, bbi = bt / Tt;
                ob = ((long)(bbi * Nn + nidx) * Tt + t) * 256;
            } else {
                ob = (long)row * 256;
            }
#pragma unroll
            for (int in = 0; in < 4; in++) {
                int col = nhalf * 128 + wnn * 32 + in * 8 + (lane & 3) * 2;
                float v0 = c[im][in][h * 2 + 0] + bias[col];
                float v1 = c[im][in][h * 2 + 1] + bias[col + 1];
                if (R) {
                    v0 += R[(long)row * 256 + col];
                    v1 += R[(long)row * 256 + col + 1];
                }
                if (relu) { v0 = fmaxf(v0, 0.f); v1 = fmaxf(v1, 0.f); }
                if (docvt) { v0 = tf2f(v0); v1 = tf2f(v1); }
                *(float2*)(Ofp + ob + col) = make_float2(v0, v1);
            }
        }
    }
}

// =====================================================================
// GEMM row-major A (R8 config): BM=64, BN=128; grid (4800,2); 3 CTAs/SM.
// Optional packed output (smem-staged, coalesced).
// =====================================================================
constexpr int AR_STRIDE = 36;
constexpr int AR_TILE = 64 * AR_STRIDE;          // 2304
constexpr int GEMM_SMEM_R = (2 * B_TILE + 2 * AR_TILE) * 4;  // 51200

__global__ __launch_bounds__(256, 3) void gemm_r(
    const float* __restrict__ Arow, const float* __restrict__ Wp,
    const float* __restrict__ bias, const float* __restrict__ R,
    float* __restrict__ Ofp, float* __restrict__ Opk,
    int relu, int trans, int docvt)
{
    extern __shared__ float sm[];
    float* Bs = sm;                      // 2 x 4096
    float* As = sm + 2 * B_TILE;         // 2 x 2304

    const int tid = threadIdx.x;
    const int lane = tid & 31, wid = tid >> 5;
    const int wmm = wid & 1;
    const int wnn = (wid >> 1) & 3;
    const int bx = blockIdx.x;
    const int m0 = bx * 64;
    const int nhalf = blockIdx.y;
    const int nb_off = nhalf * 1024;

    auto stage = [&](int kt, int b) {
        const float* asrc = Arow + (long)m0 * 256 + kt * 32;
        float* adst = As + b * AR_TILE;
#pragma unroll
        for (int j = 0; j < 2; j++) {
            int cc = j * 256 + tid;
            int row = cc >> 3, c4 = cc & 7;
            cpa16(adst + row * AR_STRIDE + c4 * 4, asrc + (long)row * 256 + c4 * 4);
        }
        const float* bsrc = Wp + kt * 8192 + nb_off;
        float* bdst = Bs + b * B_TILE;
#pragma unroll
        for (int j = 0; j < 4; j++) {
            int c = j * 256 + tid;
            int chunk = c >> 8, within = c & 255;
            cpa16(bdst + chunk * 1024 + within * 4, bsrc + chunk * 2048 + within * 4);
        }
        CP_COMMIT();
    };

    float c[2][4][4];
#pragma unroll
    for (int i = 0; i < 2; i++)
#pragma unroll
        for (int j = 0; j < 4; j++)
#pragma unroll
            for (int k2 = 0; k2 < 4; k2++) c[i][j][k2] = 0.f;

    stage(0, 0);

    for (int kt = 0; kt < 8; kt++) {
        if (kt < 7) stage(kt + 1, (kt + 1) & 1);
        if (kt < 7) { CP_WAIT(1); } else { CP_WAIT(0); }
        __syncthreads();

        const float* Ab = As + (kt & 1) * AR_TILE;
        const float* Bb = Bs + (kt & 1) * B_TILE;
#pragma unroll
        for (int ks = 0; ks < 4; ks++) {
            uint32_t a[2][4];
#pragma unroll
            for (int im = 0; im < 2; im++) {
                const float* ap = Ab + (wmm * 32 + im * 16 + (lane >> 2)) * AR_STRIDE
                                     + ks * 8 + (lane & 3);
                a[im][0] = __float_as_uint(ap[0]);
                a[im][1] = __float_as_uint(ap[8 * AR_STRIDE]);
                a[im][2] = __float_as_uint(ap[4]);
                a[im][3] = __float_as_uint(ap[8 * AR_STRIDE + 4]);
            }
#pragma unroll
            for (int in = 0; in < 4; in++) {
                const float2 bv = *(const float2*)&Bb[ks * 1024 + (wnn * 4 + in) * 64 + lane * 2];
                uint32_t b[2] = { __float_as_uint(bv.x), __float_as_uint(bv.y) };
#pragma unroll
                for (int im = 0; im < 2; im++) mma8(c[im][in], a[im], b);
            }
        }
        __syncthreads();
    }

    if (Ofp) {
#pragma unroll
        for (int im = 0; im < 2; im++) {
#pragma unroll
            for (int h = 0; h < 2; h++) {
                int row = m0 + wmm * 32 + im * 16 + (lane >> 2) + h * 8;
                long ob;
                if (trans) {
                    int bt = row / Nn;
                    int nidx = row - bt * Nn;
                    int t = bt % Tt, bbi = bt / Tt;
                    ob = ((long)(bbi * Nn + nidx) * Tt + t) * 256;
                } else {
                    ob = (long)row * 256;
                }
#pragma unroll
                for (int in = 0; in < 4; in++) {
                    int col = nhalf * 128 + wnn * 32 + in * 8 + (lane & 3) * 2;
                    float v0 = c[im][in][h * 2 + 0] + bias[col];
                    float v1 = c[im][in][h * 2 + 1] + bias[col + 1];
                    if (R) {
                        v0 += R[(long)row * 256 + col];
                        v1 += R[(long)row * 256 + col + 1];
                    }
                    if (relu) { v0 = fmaxf(v0, 0.f); v1 = fmaxf(v1, 0.f); }
                    if (docvt) { v0 = tf2f(v0); v1 = tf2f(v1); }
                    *(float2*)(Ofp + ob + col) = make_float2(v0, v1);
                }
            }
        }
    }
    if (Opk) {   // packed output: stage 64x128 in smem (scattered STS), flush coalesced
        __syncthreads();
#pragma unroll
        for (int im = 0; im < 2; im++) {
#pragma unroll
            for (int h = 0; h < 2; h++) {
                int mrow = wmm * 32 + im * 16 + (lane >> 2) + h * 8;
#pragma unroll
                for (int in = 0; in < 4; in++) {
                    int lcol = wnn * 32 + in * 8 + (lane & 3) * 2;
                    int col = nhalf * 128 + lcol;
                    float v0 = c[im][in][h * 2 + 0] + bias[col];
                    float v1 = c[im][in][h * 2 + 1] + bias[col + 1];
                    if (relu) { v0 = fmaxf(v0, 0.f); v1 = fmaxf(v1, 0.f); }
                    int off = (lcol >> 5) * 2048 + pk_off(mrow, lcol & 31);
                    sm[off]     = tf2f(v0);
                    sm[off + 4] = tf2f(v1);
                }
            }
        }
        __syncthreads();
        long base = ((long)bx * 8 + nhalf * 4) * 2048;
#pragma unroll
        for (int j = 0; j < 8; j++) {
            int idx = j * 256 + tid;             // float4 index 0..2047
            *(float4*)(Opk + base + idx * 4) = *(const float4*)(sm + idx * 4);
        }
    }
}

// =====================================================================
// Fused attention: S=q@k^T in smem, masked softmax, O=P@V -> bufY row-major
// =====================================================================
constexpr int S_STRIDE = 100;
constexpr int ATTN_SMEM = (96 * S_STRIDE + 6144) * 4;  // 62976 B

__global__ __launch_bounds__(256) void attn_fused() {
    extern __shared__ float sm[];
    float* S = sm;
    float* As = sm + 96 * S_STRIDE;
    float* Bs = As + 3072;
    float* Vs = As;

    const int head = blockIdx.x;
    const int tid = threadIdx.x, lane = tid & 31, wid = tid >> 5;
    const int wm = wid & 1, wn = wid >> 1;
    const float* qh = g_bufA + (long)head * (Tt * 256);
    const float* kh = g_bufB + (long)head * (Tt * 256);
    const float* vh = g_bufC + (long)head * (Tt * 256);

    {
        float c[3][3][4] = {};
        for (int kt = 0; kt < 256; kt += 32) {
#pragma unroll
            for (int j = 0; j < 3; j++) {
                int idx = j * 256 + tid;
                int ar = idx >> 3, ac4 = idx & 7;
                float4 v = *(const float4*)(qh + ar * 256 + kt + ac4 * 4);
                int mi = ar >> 4, r = ar & 15;
                int kii = ac4 >> 1, regb = (r >> 3) + ((ac4 & 1) << 1);
                float* dst = &As[((mi * 4 + kii) * 32 + (r & 7) * 4) * 4 + regb];
                dst[0] = v.x; dst[4] = v.y; dst[8] = v.z; dst[12] = v.w;
            }
#pragma unroll
            for (int j = 0; j < 3; j++) {
                int idx = j * 256 + tid;
                int br = idx >> 3, bc4 = idx & 7;
                float4 v = *(const float4*)(kh + br * 256 + kt + bc4 * 4);
                int ni = br >> 3, nr = br & 7;
                int kii = bc4 >> 1, regb = bc4 & 1;
                float* dst = &Bs[((ni * 4 + kii) * 32 + nr * 4) * 2 + regb];
                dst[0] = v.x; dst[2] = v.y; dst[4] = v.z; dst[6] = v.w;
            }
            __syncthreads();
#pragma unroll
            for (int ks = 0; ks < 4; ks++) {
                uint32_t a[3][4], b[3][2];
#pragma unroll
                for (int im = 0; im < 3; im++) {
                    float4 av = *(const float4*)&As[(((wm * 3 + im) * 4 + ks) * 32 + lane) * 4];
                    a[im][0] = __float_as_uint(av.x); a[im][1] = __float_as_uint(av.y);
                    a[im][2] = __float_as_uint(av.z); a[im][3] = __float_as_uint(av.w);
                }
#pragma unroll
                for (int in = 0; in < 3; in++) {
                    float2 bv = *(const float2*)&Bs[(((wn * 3 + in) * 4 + ks) * 32 + lane) * 2];
                    b[in][0] = __float_as_uint(bv.x); b[in][1] = __float_as_uint(bv.y);
                }
#pragma unroll
                for (int im = 0; im < 3; im++)
#pragma unroll
                    for (int in = 0; in < 3; in++)
                        mma8(c[im][in], a[im], b[in]);
            }
            __syncthreads();
        }
#pragma unroll
        for (int im = 0; im < 3; im++)
#pragma unroll
            for (int h = 0; h < 2; h++) {
                int row = wm * 48 + im * 16 + (lane >> 2) + h * 8;
#pragma unroll
                for (int in = 0; in < 3; in++) {
                    int col = wn * 24 + in * 8 + (lane & 3) * 2;
                    *(float2*)(S + row * S_STRIDE + col) =
                        make_float2(c[im][in][h * 2], c[im][in][h * 2 + 1]);
                }
            }
    }
    __syncthreads();

#pragma unroll
    for (int r = 0; r < 12; r++) {
        int row = wid * 12 + r;
        float* p = S + row * S_STRIDE;
        float x[3];
#pragma unroll
        for (int j = 0; j < 3; j++) {
            int col = lane + j * 32;
            float s = p[col];
            x[j] = (col <= row) ? s * 0.0625f : (-32767.0f * 0.0625f);
        }
        float mx = fmaxf(x[0], fmaxf(x[1], x[2]));
#pragma unroll
        for (int o = 16; o > 0; o >>= 1) mx = fmaxf(mx, __shfl_xor_sync(0xffffffffu, mx, o));
        float e0 = __expf(x[0] - mx), e1 = __expf(x[1] - mx), e2 = __expf(x[2] - mx);
        float sum = e0 + e1 + e2;
#pragma unroll
        for (int o = 16; o > 0; o >>= 1) sum += __shfl_xor_sync(0xffffffffu, sum, o);
        float inv = 1.0f / sum;
        p[lane]      = tf2f(e0 * inv);
        p[lane + 32] = tf2f(e1 * inv);
        p[lane + 64] = tf2f(e2 * inv);
    }
    __syncthreads();

    const int bbi = head / Nn, nh = head % Nn;
    for (int n0 = 0; n0 < 256; n0 += 64) {
#pragma unroll
        for (int j = 0; j < 6; j++) {
            int idx = j * 256 + tid;
            int sr = idx >> 4, f4 = idx & 15;
            float4 vv = *(const float4*)(vh + sr * 256 + n0 + f4 * 4);
            int kt = sr >> 5, srl = sr & 31;
            int ni = f4 >> 1;
            int kii = srl >> 3;
            int regb = (srl >> 2) & 1;
            int lb = (f4 & 1) * 16 + (srl & 3);
            float* dst = &Vs[kt * 2048 + ((ni * 4 + kii) * 32) * 2 + regb];
            dst[(lb + 0) * 2]  = vv.x;
            dst[(lb + 4) * 2]  = vv.y;
            dst[(lb + 8) * 2]  = vv.z;
            dst[(lb + 12) * 2] = vv.w;
        }
        __syncthreads();

        float c[3][2][4] = {};
#pragma unroll
        for (int kt = 0; kt < 3; kt++) {
#pragma unroll
            for (int ks = 0; ks < 4; ks++) {
                uint32_t a[3][4], b[2][2];
#pragma unroll
                for (int im = 0; im < 3; im++) {
                    const float* ap = S + (wm * 48 + im * 16 + (lane >> 2)) * S_STRIDE
                                        + kt * 32 + ks * 8 + (lane & 3);
                    a[im][0] = __float_as_uint(ap[0]);
                    a[im][1] = __float_as_uint(ap[8 * S_STRIDE]);
                    a[im][2] = __float_as_uint(ap[4]);
                    a[im][3] = __float_as_uint(ap[8 * S_STRIDE + 4]);
                }
#pragma unroll
                for (int in = 0; in < 2; in++) {
                    float2 bv = *(const float2*)&Vs[kt * 2048 +
                        (((wn * 2 + in) * 4 + ks) * 32 + lane) * 2];
                    b[in][0] = __float_as_uint(bv.x); b[in][1] = __float_as_uint(bv.y);
                }
#pragma unroll
                for (int im = 0; im < 3; im++)
#pragma unroll
                    for (int in = 0; in < 2; in++)
                        mma8(c[im][in], a[im], b[in]);
            }
        }
#pragma unroll
        for (int im = 0; im < 3; im++)
#pragma unroll
            for (int h = 0; h < 2; h++) {
                int t = wm * 48 + im * 16 + (lane >> 2) + h * 8;
                long ob = ((long)(bbi * Tt + t) * Nn + nh) * 256;
#pragma unroll
                for (int in = 0; in < 2; in++) {
                    int f = n0 + wn * 16 + in * 8 + (lane & 3) * 2;
                    *(float2*)(g_bufY + ob + f) =
                        make_float2(tf2f(c[im][in][h * 2]), tf2f(c[im][in][h * 2 + 1]));
                }
            }
        __syncthreads();
    }
}

// =====================================================================
// LayerNorm over F=256. One warp per row. Optional tf32-rounded output.
// =====================================================================
__global__ __launch_bounds__(256) void ln_k(
    const float* __restrict__ in, float* __restrict__ outfp, int docvt)
{
    long row = (long)blockIdx.x * 8 + (threadIdx.x >> 5);
    int lane = threadIdx.x & 31;
    const float* p = in + row * 256;
    float4 a = *(const float4*)(p + lane * 4);
    float4 b = *(const float4*)(p + 128 + lane * 4);
    float s = a.x + a.y + a.z + a.w + b.x + b.y + b.z + b.w;
    float q = a.x * a.x + a.y * a.y + a.z * a.z + a.w * a.w +
              b.x * b.x + b.y * b.y + b.z * b.z + b.w * b.w;
#pragma unroll
    for (int o = 16; o > 0; o >>= 1) {
        s += __shfl_xor_sync(0xffffffffu, s, o);
        q += __shfl_xor_sync(0xffffffffu, q, o);
    }
    float mean = s * (1.0f / 256.0f);
    float var = q * (1.0f / 256.0f) - mean * mean;
    float rs = rsqrtf(var + 1e-5f);
    float4 oa = make_float4((a.x - mean) * rs, (a.y - mean) * rs,
                            (a.z - mean) * rs, (a.w - mean) * rs);
    float4 ob = make_float4((b.x - mean) * rs, (b.y - mean) * rs,
                            (b.z - mean) * rs, (b.w - mean) * rs);
    if (docvt) {
        oa.x = tf2f(oa.x); oa.y = tf2f(oa.y); oa.z = tf2f(oa.z); oa.w = tf2f(oa.w);
        ob.x = tf2f(ob.x); ob.y = tf2f(ob.y); ob.z = tf2f(ob.z); ob.w = tf2f(ob.w);
    }
    float* op = outfp + row * 256;
    *(float4*)(op + lane * 4) = oa;
    *(float4*)(op + 128 + lane * 4) = ob;
}

// =====================================================================
extern "C" void kernel_launch(void* const* d_in, const int* in_sizes, int n_in,
                              void* d_out, int out_size) {
    const float* xl  = (const float*)d_in[0];
    const float* xh  = (const float*)d_in[1];
    const float* te  = (const float*)d_in[2];
    const float* Wq  = (const float*)d_in[3];
    const float* bq  = (const float*)d_in[4];
    const float* Wk  = (const float*)d_in[5];
    const float* bk  = (const float*)d_in[6];
    const float* Wv  = (const float*)d_in[7];
    const float* bv  = (const float*)d_in[8];
    const float* Wo  = (const float*)d_in[9];
    const float* bo  = (const float*)d_in[10];
    const float* Wf1 = (const float*)d_in[11];
    const float* bf1 = (const float*)d_in[12];
    const float* Wf2 = (const float*)d_in[13];
    const float* bf2 = (const float*)d_in[14];
    float* out = (float*)d_out;

    static bool init = false;
    static float *wbase, *bA, *bB, *bC, *bX, *bY, *pH, *pHH;
    if (!init) {
        cudaFuncSetAttribute(gemm_p, cudaFuncAttributeMaxDynamicSharedMemorySize, GEMM_SMEM_P);
        cudaFuncSetAttribute(gemm_r, cudaFuncAttributeMaxDynamicSharedMemorySize, GEMM_SMEM_R);
        cudaFuncSetAttribute(attn_fused, cudaFuncAttributeMaxDynamicSharedMemorySize, ATTN_SMEM);
        cudaGetSymbolAddress((void**)&wbase, g_bufW);
        cudaGetSymbolAddress((void**)&bA, g_bufA);
        cudaGetSymbolAddress((void**)&bB, g_bufB);
        cudaGetSymbolAddress((void**)&bC, g_bufC);
        cudaGetSymbolAddress((void**)&bX, g_bufX);
        cudaGetSymbolAddress((void**)&bY, g_bufY);
        cudaGetSymbolAddress((void**)&pH, g_PH);
        cudaGetSymbolAddress((void**)&pHH, g_PHH);
        init = true;
    }

    prep_x<<<Mtot / 64, 256>>>(xl, xh, te);
    pack_w6<<<1536, 256>>>(Wq, Wk, Wv, Wo, Wf1, Wf2);

    dim3 gg(Mtot / 64, 2);   // 4800 x 2 CTAs per dense GEMM

    // q = X @ Wq^T + bq            -> bufA [B,N,T,F], tf32-rounded
    gemm_r<<<gg, 256, GEMM_SMEM_R>>>(bX, wbase + 0 * 65536, bq, nullptr, bA, nullptr, 0, 1, 1);
    // k = relu(H @ Wk^T + bk)      -> bufB [B,N,T,F]
    gemm_p<<<gg, 256, GEMM_SMEM_P>>>(pH, wbase + 1 * 65536, bk, nullptr, bB, 1, 1, 1);
    // v = relu(H @ Wv^T + bv)      -> bufC [B,N,T,F]
    gemm_p<<<gg, 256, GEMM_SMEM_P>>>(pH, wbase + 2 * 65536, bv, nullptr, bC, 1, 1, 1);

    attn_fused<<<HEADS, 256, ATTN_SMEM>>>();       // -> bufY row-major (tf32)

    // preLN1 = Y @ Wo^T + bo + X   -> bufA fp32 row-major
    gemm_r<<<gg, 256, GEMM_SMEM_R>>>(bY, wbase + 3 * 65536, bo, bX, bA, nullptr, 0, 0, 0);
    // out1 = LN(preLN1), tf32-rounded, in place
    ln_k<<<Mtot / 8, 256>>>(bA, bA, 1);

    // h = relu(out1 @ Wf1^T + bf1) -> pHH packed only
    gemm_r<<<gg, 256, GEMM_SMEM_R>>>(bA, wbase + 4 * 65536, bf1, nullptr, nullptr, pHH, 1, 0, 0);
    // preLN2 = h @ Wf2^T + bf2 + out1 -> bufB fp32
    gemm_p<<<gg, 256, GEMM_SMEM_P>>>(pHH, wbase + 5 * 65536, bf2, bA, bB, 0, 0, 0);
    ln_k<<<Mtot / 8, 256>>>(bB, out, 0);           // final LN -> d_out
}

// round 17
// speedup vs baseline: 1.0662x; 1.0119x over previous
#include <cuda_runtime.h>
#include <cstdint>

#define DINL __device__ __forceinline__

constexpr int Tt = 96, Nn = 400, Fd = 256;
constexpr int Bb = 8;
constexpr int Mtot = Bb * Tt * Nn;              // 307200
constexpr int HEADS = Bb * Nn;                  // 3200
constexpr long BUF_ELEMS = (long)Mtot * Fd;     // 78,643,200

// ---------------- scratch (device globals; no allocation APIs) ----------------
__device__ float g_bufA[BUF_ELEMS];   // q [B,N,T,F] -> preLN1 fp32
__device__ float g_bufB[BUF_ELEMS];   // k [B,N,T,F] -> preLN2 fp32
__device__ float g_bufC[BUF_ELEMS];   // v [B,N,T,F]
__device__ float g_bufX[BUF_ELEMS];   // tf32(xl + te) row-major (residual + q-GEMM A)
__device__ float g_bufY[BUF_ELEMS];   // attention out row-major [B,T,N,F] (tf32)
__device__ float g_PH[BUF_ELEMS];     // packed tf32(xh+te), 64x32 fragment tiles
__device__ float g_PHH[BUF_ELEMS];    // packed relu(ff1)
__device__ float g_bufW[6 * 256 * 256];  // packed tf32 weight fragments
__device__ float2 g_stats[Mtot];      // LN1 per-row {mean, rstd}

// ---------------- tf32 + async-copy helpers ----------------
DINL uint32_t f2tf(float x) {
    uint32_t r;
    asm("cvt.rna.tf32.f32 %0, %1;" : "=r"(r) : "f"(x));
    return r;
}
DINL float tf2f(float x) { return __uint_as_float(f2tf(x)); }

DINL void mma8(float* c, const uint32_t* a, const uint32_t* b) {
    asm volatile(
        "mma.sync.aligned.m16n8k8.row.col.f32.tf32.tf32.f32 "
        "{%0,%1,%2,%3}, {%4,%5,%6,%7}, {%8,%9}, {%0,%1,%2,%3};"
        : "+f"(c[0]), "+f"(c[1]), "+f"(c[2]), "+f"(c[3])
        : "r"(a[0]), "r"(a[1]), "r"(a[2]), "r"(a[3]), "r"(b[0]), "r"(b[1]));
}

DINL void cpa16(float* smem_dst, const float* gsrc) {
    uint32_t d = (uint32_t)__cvta_generic_to_shared(smem_dst);
    asm volatile("cp.async.cg.shared.global [%0], [%1], 16;\n" :: "r"(d), "l"(gsrc));
}
#define CP_COMMIT()  asm volatile("cp.async.commit_group;\n")
#define CP_WAIT(n)   asm volatile("cp.async.wait_group %0;\n" :: "n"(n))

// packed-tile inner offset for (mrow in [0,64), kc32 in [0,32))
DINL int pk_off(int mrow, int kc32) {
    int mi = mrow >> 4, r = mrow & 15, kii = kc32 >> 3, kc = kc32 & 7;
    return ((mi * 4 + kii) * 32 + (r & 7) * 4 + (kc & 3)) * 4 + (r >> 3) + ((kc >> 2) << 1);
}

// =====================================================================
// Pre-pass: bufX = tf32(xl+te) row-major;  PH = packed tf32(xh+te)
// =====================================================================
__global__ __launch_bounds__(256) void prep_x(
    const float* __restrict__ xl, const float* __restrict__ xh,
    const float* __restrict__ te)
{
    __shared__ float sH[2048];
    const int mt = blockIdx.x, m0 = mt * 64, tid = threadIdx.x;
    for (int ks = 0; ks < 8; ks++) {
#pragma unroll
        for (int j = 0; j < 2; j++) {
            int cc = j * 256 + tid;          // 0..511
            int r = cc >> 3, c4 = cc & 7;
            int m = m0 + r;
            long g = (long)m * 256 + ks * 32 + c4 * 4;
            int bt = m / Nn;
            float4 t4 = *(const float4*)(te + bt * 256 + ks * 32 + c4 * 4);
            float4 a = *(const float4*)(xl + g);
            float4 b = *(const float4*)(xh + g);
            a.x = tf2f(a.x + t4.x); a.y = tf2f(a.y + t4.y);
            a.z = tf2f(a.z + t4.z); a.w = tf2f(a.w + t4.w);
            b.x += t4.x; b.y += t4.y; b.z += t4.z; b.w += t4.w;
            *(float4*)(g_bufX + g) = a;
            int k0 = c4 * 4;
            sH[pk_off(r, k0 + 0)] = tf2f(b.x); sH[pk_off(r, k0 + 1)] = tf2f(b.y);
            sH[pk_off(r, k0 + 2)] = tf2f(b.z); sH[pk_off(r, k0 + 3)] = tf2f(b.w);
        }
        __syncthreads();
        long base = ((long)mt * 8 + ks) * 2048;
#pragma unroll
        for (int j = 0; j < 2; j++) {
            int idx = j * 256 + tid;
            *(float4*)(g_PH + base + idx * 4) = *(const float4*)(sH + idx * 4);
        }
        __syncthreads();
    }
}

// =====================================================================
// Pack all 6 weights [256x256] (W[n][k]) into B fragment layout.
// =====================================================================
__global__ __launch_bounds__(256) void pack_w6(
    const float* __restrict__ W0, const float* __restrict__ W1,
    const float* __restrict__ W2, const float* __restrict__ W3,
    const float* __restrict__ W4, const float* __restrict__ W5)
{
    int widx = blockIdx.x >> 8;
    const float* W;
    switch (widx) {
        case 0: W = W0; break;
        case 1: W = W1; break;
        case 2: W = W2; break;
        case 3: W = W3; break;
        case 4: W = W4; break;
        default: W = W5; break;
    }
    int i = (blockIdx.x & 255) * 256 + threadIdx.x;  // 0..65535
    int n = i >> 8, k = i & 255;
    int kb = k >> 3, nb = n >> 3;
    int lanei = (n & 7) * 4 + (k & 3);
    int reg = (k >> 2) & 1;
    g_bufW[widx * 65536 + ((kb * 32 + nb) * 32 + lanei) * 2 + reg] = tf2f(W[i]);
}

constexpr int A_TILE = 2048;
constexpr int B_TILE = 4096;

// =====================================================================
// gemm_kv: dual-B packed-A GEMM. Computes k AND v in one pass over PH.
// BM=64, BN=128, BK=32; 256 thr (2m x 4n); grid (4800, 2); 2 CTAs/SM.
// =====================================================================
constexpr int GEMM_SMEM_KV = (2 * A_TILE + 4 * B_TILE) * 4;   // 81920

__global__ __launch_bounds__(256, 2) void gemm_kv(
    const float* __restrict__ Apk,
    const float* __restrict__ Wp1, const float* __restrict__ Wp2,
    const float* __restrict__ bias1, const float* __restrict__ bias2,
    float* __restrict__ O1, float* __restrict__ O2)
{
    extern __shared__ float sm[];
    float* B1s = sm;                     // 2 x 4096
    float* B2s = sm + 2 * B_TILE;        // 2 x 4096
    float* As  = sm + 4 * B_TILE;        // 2 x 2048

    const int tid = threadIdx.x;
    const int lane = tid & 31, wid = tid >> 5;
    const int wmm = wid & 1;
    const int wnn = (wid >> 1) & 3;
    const int m0 = blockIdx.x * 64;
    const int nhalf = blockIdx.y;
    const int nb_off = nhalf * 1024;
    const float* Abase = Apk + (long)blockIdx.x * 16384;

    auto stage = [&](int kt, int b) {
        const float* asrc = Abase + kt * 2048;
        float* adst = As + b * A_TILE;
#pragma unroll
        for (int j = 0; j < 2; j++) {
            int c = j * 256 + tid;
            cpa16(adst + c * 4, asrc + c * 4);
        }
        const float* b1src = Wp1 + kt * 8192 + nb_off;
        const float* b2src = Wp2 + kt * 8192 + nb_off;
        float* b1dst = B1s + b * B_TILE;
        float* b2dst = B2s + b * B_TILE;
#pragma unroll
        for (int j = 0; j < 4; j++) {
            int c = j * 256 + tid;
            int chunk = c >> 8, within = c & 255;
            cpa16(b1dst + chunk * 1024 + within * 4, b1src + chunk * 2048 + within * 4);
            cpa16(b2dst + chunk * 1024 + within * 4, b2src + chunk * 2048 + within * 4);
        }
        CP_COMMIT();
    };

    float c1[2][4][4], c2[2][4][4];
#pragma unroll
    for (int i = 0; i < 2; i++)
#pragma unroll
        for (int j = 0; j < 4; j++)
#pragma unroll
            for (int k2 = 0; k2 < 4; k2++) { c1[i][j][k2] = 0.f; c2[i][j][k2] = 0.f; }

    stage(0, 0);

    for (int kt = 0; kt < 8; kt++) {
        if (kt < 7) stage(kt + 1, (kt + 1) & 1);
        if (kt < 7) { CP_WAIT(1); } else { CP_WAIT(0); }
        __syncthreads();

        const float* Ab = As + (kt & 1) * A_TILE;
        const float* B1b = B1s + (kt & 1) * B_TILE;
        const float* B2b = B2s + (kt & 1) * B_TILE;
#pragma unroll
        for (int ks = 0; ks < 4; ks++) {
            uint32_t a[2][4];
#pragma unroll
            for (int im = 0; im < 2; im++) {
                float4 av = *(const float4*)(Ab + ((wmm * 2 + im) * 4 + ks) * 128 + lane * 4);
                a[im][0] = __float_as_uint(av.x); a[im][1] = __float_as_uint(av.y);
                a[im][2] = __float_as_uint(av.z); a[im][3] = __float_as_uint(av.w);
            }
#pragma unroll
            for (int in = 0; in < 4; in++) {
                int boff = ks * 1024 + (wnn * 4 + in) * 64 + lane * 2;
                const float2 bv1 = *(const float2*)&B1b[boff];
                const float2 bv2 = *(const float2*)&B2b[boff];
                uint32_t b1[2] = { __float_as_uint(bv1.x), __float_as_uint(bv1.y) };
                uint32_t b2[2] = { __float_as_uint(bv2.x), __float_as_uint(bv2.y) };
#pragma unroll
                for (int im = 0; im < 2; im++) {
                    mma8(c1[im][in], a[im], b1);
                    mma8(c2[im][in], a[im], b2);
                }
            }
        }
        __syncthreads();
    }

#pragma unroll
    for (int im = 0; im < 2; im++) {
#pragma unroll
        for (int h = 0; h < 2; h++) {
            int row = m0 + wmm * 32 + im * 16 + (lane >> 2) + h * 8;
            int bt = row / Nn;
            int nidx = row - bt * Nn;
            int t = bt % Tt, bbi = bt / Tt;
            long ob = ((long)(bbi * Nn + nidx) * Tt + t) * 256;
#pragma unroll
            for (int in = 0; in < 4; in++) {
                int col = nhalf * 128 + wnn * 32 + in * 8 + (lane & 3) * 2;
                float k0 = fmaxf(c1[im][in][h * 2 + 0] + bias1[col], 0.f);
                float k1 = fmaxf(c1[im][in][h * 2 + 1] + bias1[col + 1], 0.f);
                float v0 = fmaxf(c2[im][in][h * 2 + 0] + bias2[col], 0.f);
                float v1 = fmaxf(c2[im][in][h * 2 + 1] + bias2[col + 1], 0.f);
                *(float2*)(O1 + ob + col) = make_float2(tf2f(k0), tf2f(k1));
                *(float2*)(O2 + ob + col) = make_float2(tf2f(v0), tf2f(v1));
            }
        }
    }
}

// =====================================================================
// gemm_p (R12 config), with optional LN-residual via stats (FF2).
// =====================================================================
constexpr int GEMM_SMEM_P = (2 * B_TILE + 2 * A_TILE) * 4;   // 49152

__global__ __launch_bounds__(256, 3) void gemm_p(
    const float* __restrict__ Apk, const float* __restrict__ Wp,
    const float* __restrict__ bias, const float* __restrict__ R,
    const float2* __restrict__ stats,
    float* __restrict__ Ofp,
    int relu, int trans, int docvt)
{
    extern __shared__ float sm[];
    float* Bs = sm;
    float* As = sm + 2 * B_TILE;

    const int tid = threadIdx.x;
    const int lane = tid & 31, wid = tid >> 5;
    const int wmm = wid & 1;
    const int wnn = (wid >> 1) & 3;
    const int m0 = blockIdx.x * 64;
    const int nhalf = blockIdx.y;
    const int nb_off = nhalf * 1024;
    const float* Abase = Apk + (long)blockIdx.x * 16384;

    auto stage = [&](int kt, int b) {
        const float* asrc = Abase + kt * 2048;
        float* adst = As + b * A_TILE;
#pragma unroll
        for (int j = 0; j < 2; j++) {
            int c = j * 256 + tid;
            cpa16(adst + c * 4, asrc + c * 4);
        }
        const float* bsrc = Wp + kt * 8192 + nb_off;
        float* bdst = Bs + b * B_TILE;
#pragma unroll
        for (int j = 0; j < 4; j++) {
            int c = j * 256 + tid;
            int chunk = c >> 8, within = c & 255;
            cpa16(bdst + chunk * 1024 + within * 4, bsrc + chunk * 2048 + within * 4);
        }
        CP_COMMIT();
    };

    float c[2][4][4];
#pragma unroll
    for (int i = 0; i < 2; i++)
#pragma unroll
        for (int j = 0; j < 4; j++)
#pragma unroll
            for (int k2 = 0; k2 < 4; k2++) c[i][j][k2] = 0.f;

    stage(0, 0);

    for (int kt = 0; kt < 8; kt++) {
        if (kt < 7) stage(kt + 1, (kt + 1) & 1);
        if (kt < 7) { CP_WAIT(1); } else { CP_WAIT(0); }
        __syncthreads();

        const float* Ab = As + (kt & 1) * A_TILE;
        const float* Bb = Bs + (kt & 1) * B_TILE;
#pragma unroll
        for (int ks = 0; ks < 4; ks++) {
            uint32_t a[2][4];
#pragma unroll
            for (int im = 0; im < 2; im++) {
                float4 av = *(const float4*)(Ab + ((wmm * 2 + im) * 4 + ks) * 128 + lane * 4);
                a[im][0] = __float_as_uint(av.x); a[im][1] = __float_as_uint(av.y);
                a[im][2] = __float_as_uint(av.z); a[im][3] = __float_as_uint(av.w);
            }
#pragma unroll
            for (int in = 0; in < 4; in++) {
                const float2 bv = *(const float2*)&Bb[ks * 1024 + (wnn * 4 + in) * 64 + lane * 2];
                uint32_t b[2] = { __float_as_uint(bv.x), __float_as_uint(bv.y) };
#pragma unroll
                for (int im = 0; im < 2; im++) mma8(c[im][in], a[im], b);
            }
        }
        __syncthreads();
    }

#pragma unroll
    for (int im = 0; im < 2; im++) {
#pragma unroll
        for (int h = 0; h < 2; h++) {
            int row = m0 + wmm * 32 + im * 16 + (lane >> 2) + h * 8;
            long ob;
            if (trans) {
                int bt = row / Nn;
                int nidx = row - bt * Nn;
                int t = bt % Tt, bbi = bt / Tt;
                ob = ((long)(bbi * Nn + nidx) * Tt + t) * 256;
            } else {
                ob = (long)row * 256;
            }
            float sc = 0.f, sh = 0.f;
            if (stats) {
                float2 st = stats[row];
                sc = st.y; sh = -st.x * st.y;
            }
#pragma unroll
            for (int in = 0; in < 4; in++) {
                int col = nhalf * 128 + wnn * 32 + in * 8 + (lane & 3) * 2;
                float v0 = c[im][in][h * 2 + 0] + bias[col];
                float v1 = c[im][in][h * 2 + 1] + bias[col + 1];
                if (R) {
                    float r0 = R[(long)row * 256 + col];
                    float r1 = R[(long)row * 256 + col + 1];
                    if (stats) {
                        r0 = tf2f(fmaf(r0, sc, sh));
                        r1 = tf2f(fmaf(r1, sc, sh));
                    }
                    v0 += r0; v1 += r1;
                }
                if (relu) { v0 = fmaxf(v0, 0.f); v1 = fmaxf(v1, 0.f); }
                if (docvt) { v0 = tf2f(v0); v1 = tf2f(v1); }
                *(float2*)(Ofp + ob + col) = make_float2(v0, v1);
            }
        }
    }
}

// =====================================================================
// gemm_r (row-major A), template LNA: apply LN to A fragments (FF1).
// Optional packed output (smem-staged) and row-major output.
// =====================================================================
constexpr int AR_STRIDE = 36;
constexpr int AR_TILE = 64 * AR_STRIDE;          // 2304
constexpr int GEMM_SMEM_R = (2 * B_TILE + 2 * AR_TILE) * 4;  // 51200

template <int LNA>
__global__ __launch_bounds__(256, 3) void gemm_r(
    const float* __restrict__ Arow, const float* __restrict__ Wp,
    const float* __restrict__ bias, const float* __restrict__ R,
    const float2* __restrict__ stats,
    float* __restrict__ Ofp, float* __restrict__ Opk,
    int relu, int trans, int docvt)
{
    extern __shared__ float sm[];
    float* Bs = sm;
    float* As = sm + 2 * B_TILE;

    const int tid = threadIdx.x;
    const int lane = tid & 31, wid = tid >> 5;
    const int wmm = wid & 1;
    const int wnn = (wid >> 1) & 3;
    const int bx = blockIdx.x;
    const int m0 = bx * 64;
    const int nhalf = blockIdx.y;
    const int nb_off = nhalf * 1024;

    // per-thread A-row LN constants (rows base, base+8, base+16, base+24)
    float asc[4], ash[4];
    if (LNA) {
        int base = m0 + wmm * 32 + (lane >> 2);
#pragma unroll
        for (int j = 0; j < 4; j++) {
            float2 st = stats[base + j * 8];
            asc[j] = st.y; ash[j] = -st.x * st.y;
        }
    }

    auto stage = [&](int kt, int b) {
        const float* asrc = Arow + (long)m0 * 256 + kt * 32;
        float* adst = As + b * AR_TILE;
#pragma unroll
        for (int j = 0; j < 2; j++) {
            int cc = j * 256 + tid;
            int row = cc >> 3, c4 = cc & 7;
            cpa16(adst + row * AR_STRIDE + c4 * 4, asrc + (long)row * 256 + c4 * 4);
        }
        const float* bsrc = Wp + kt * 8192 + nb_off;
        float* bdst = Bs + b * B_TILE;
#pragma unroll
        for (int j = 0; j < 4; j++) {
            int c = j * 256 + tid;
            int chunk = c >> 8, within = c & 255;
            cpa16(bdst + chunk * 1024 + within * 4, bsrc + chunk * 2048 + within * 4);
        }
        CP_COMMIT();
    };

    float c[2][4][4];
#pragma unroll
    for (int i = 0; i < 2; i++)
#pragma unroll
        for (int j = 0; j < 4; j++)
#pragma unroll
            for (int k2 = 0; k2 < 4; k2++) c[i][j][k2] = 0.f;

    stage(0, 0);

    for (int kt = 0; kt < 8; kt++) {
        if (kt < 7) stage(kt + 1, (kt + 1) & 1);
        if (kt < 7) { CP_WAIT(1); } else { CP_WAIT(0); }
        __syncthreads();

        const float* Ab = As + (kt & 1) * AR_TILE;
        const float* Bb = Bs + (kt & 1) * B_TILE;
#pragma unroll
        for (int ks = 0; ks < 4; ks++) {
            uint32_t a[2][4];
#pragma unroll
            for (int im = 0; im < 2; im++) {
                const float* ap = Ab + (wmm * 32 + im * 16 + (lane >> 2)) * AR_STRIDE
                                     + ks * 8 + (lane & 3);
                if (LNA) {
                    int j0 = im * 2, j1 = im * 2 + 1;
                    a[im][0] = f2tf(fmaf(ap[0],                 asc[j0], ash[j0]));
                    a[im][1] = f2tf(fmaf(ap[8 * AR_STRIDE],     asc[j1], ash[j1]));
                    a[im][2] = f2tf(fmaf(ap[4],                 asc[j0], ash[j0]));
                    a[im][3] = f2tf(fmaf(ap[8 * AR_STRIDE + 4], asc[j1], ash[j1]));
                } else {
                    a[im][0] = __float_as_uint(ap[0]);
                    a[im][1] = __float_as_uint(ap[8 * AR_STRIDE]);
                    a[im][2] = __float_as_uint(ap[4]);
                    a[im][3] = __float_as_uint(ap[8 * AR_STRIDE + 4]);
                }
            }
#pragma unroll
            for (int in = 0; in < 4; in++) {
                const float2 bv = *(const float2*)&Bb[ks * 1024 + (wnn * 4 + in) * 64 + lane * 2];
                uint32_t b[2] = { __float_as_uint(bv.x), __float_as_uint(bv.y) };
#pragma unroll
                for (int im = 0; im < 2; im++) mma8(c[im][in], a[im], b);
            }
        }
        __syncthreads();
    }

    if (Ofp) {
#pragma unroll
        for (int im = 0; im < 2; im++) {
#pragma unroll
            for (int h = 0; h < 2; h++) {
                int row = m0 + wmm * 32 + im * 16 + (lane >> 2) + h * 8;
                long ob;
                if (trans) {
                    int bt = row / Nn;
                    int nidx = row - bt * Nn;
                    int t = bt % Tt, bbi = bt / Tt;
                    ob = ((long)(bbi * Nn + nidx) * Tt + t) * 256;
                } else {
                    ob = (long)row * 256;
                }
#pragma unroll
                for (int in = 0; in < 4; in++) {
                    int col = nhalf * 128 + wnn * 32 + in * 8 + (lane & 3) * 2;
                    float v0 = c[im][in][h * 2 + 0] + bias[col];
                    float v1 = c[im][in][h * 2 + 1] + bias[col + 1];
                    if (R) {
                        v0 += R[(long)row * 256 + col];
                        v1 += R[(long)row * 256 + col + 1];
                    }
                    if (relu) { v0 = fmaxf(v0, 0.f); v1 = fmaxf(v1, 0.f); }
                    if (docvt) { v0 = tf2f(v0); v1 = tf2f(v1); }
                    *(float2*)(Ofp + ob + col) = make_float2(v0, v1);
                }
            }
        }
    }
    if (Opk) {
        __syncthreads();
#pragma unroll
        for (int im = 0; im < 2; im++) {
#pragma unroll
            for (int h = 0; h < 2; h++) {
                int mrow = wmm * 32 + im * 16 + (lane >> 2) + h * 8;
#pragma unroll
                for (int in = 0; in < 4; in++) {
                    int lcol = wnn * 32 + in * 8 + (lane & 3) * 2;
                    int col = nhalf * 128 + lcol;
                    float v0 = c[im][in][h * 2 + 0] + bias[col];
                    float v1 = c[im][in][h * 2 + 1] + bias[col + 1];
                    if (relu) { v0 = fmaxf(v0, 0.f); v1 = fmaxf(v1, 0.f); }
                    int off = (lcol >> 5) * 2048 + pk_off(mrow, lcol & 31);
                    sm[off]     = tf2f(v0);
                    sm[off + 4] = tf2f(v1);
                }
            }
        }
        __syncthreads();
        long base = ((long)bx * 8 + nhalf * 4) * 2048;
#pragma unroll
        for (int j = 0; j < 8; j++) {
            int idx = j * 256 + tid;
            *(float4*)(Opk + base + idx * 4) = *(const float4*)(sm + idx * 4);
        }
    }
}

// =====================================================================
// Fused attention: S=q@k^T in smem, masked softmax, O=P@V -> bufY row-major
// =====================================================================
constexpr int S_STRIDE = 100;
constexpr int ATTN_SMEM = (96 * S_STRIDE + 6144) * 4;  // 62976 B

__global__ __launch_bounds__(256) void attn_fused() {
    extern __shared__ float sm[];
    float* S = sm;
    float* As = sm + 96 * S_STRIDE;
    float* Bs = As + 3072;
    float* Vs = As;

    const int head = blockIdx.x;
    const int tid = threadIdx.x, lane = tid & 31, wid = tid >> 5;
    const int wm = wid & 1, wn = wid >> 1;
    const float* qh = g_bufA + (long)head * (Tt * 256);
    const float* kh = g_bufB + (long)head * (Tt * 256);
    const float* vh = g_bufC + (long)head * (Tt * 256);

    {
        float c[3][3][4] = {};
        for (int kt = 0; kt < 256; kt += 32) {
#pragma unroll
            for (int j = 0; j < 3; j++) {
                int idx = j * 256 + tid;
                int ar = idx >> 3, ac4 = idx & 7;
                float4 v = *(const float4*)(qh + ar * 256 + kt + ac4 * 4);
                int mi = ar >> 4, r = ar & 15;
                int kii = ac4 >> 1, regb = (r >> 3) + ((ac4 & 1) << 1);
                float* dst = &As[((mi * 4 + kii) * 32 + (r & 7) * 4) * 4 + regb];
                dst[0] = v.x; dst[4] = v.y; dst[8] = v.z; dst[12] = v.w;
            }
#pragma unroll
            for (int j = 0; j < 3; j++) {
                int idx = j * 256 + tid;
                int br = idx >> 3, bc4 = idx & 7;
                float4 v = *(const float4*)(kh + br * 256 + kt + bc4 * 4);
                int ni = br >> 3, nr = br & 7;
                int kii = bc4 >> 1, regb = bc4 & 1;
                float* dst = &Bs[((ni * 4 + kii) * 32 + nr * 4) * 2 + regb];
                dst[0] = v.x; dst[2] = v.y; dst[4] = v.z; dst[6] = v.w;
            }
            __syncthreads();
#pragma unroll
            for (int ks = 0; ks < 4; ks++) {
                uint32_t a[3][4], b[3][2];
#pragma unroll
                for (int im = 0; im < 3; im++) {
                    float4 av = *(const float4*)&As[(((wm * 3 + im) * 4 + ks) * 32 + lane) * 4];
                    a[im][0] = __float_as_uint(av.x); a[im][1] = __float_as_uint(av.y);
                    a[im][2] = __float_as_uint(av.z); a[im][3] = __float_as_uint(av.w);
                }
#pragma unroll
                for (int in = 0; in < 3; in++) {
                    float2 bv = *(const float2*)&Bs[(((wn * 3 + in) * 4 + ks) * 32 + lane) * 2];
                    b[in][0] = __float_as_uint(bv.x); b[in][1] = __float_as_uint(bv.y);
                }
#pragma unroll
                for (int im = 0; im < 3; im++)
#pragma unroll
                    for (int in = 0; in < 3; in++)
                        mma8(c[im][in], a[im], b[in]);
            }
            __syncthreads();
        }
#pragma unroll
        for (int im = 0; im < 3; im++)
#pragma unroll
            for (int h = 0; h < 2; h++) {
                int row = wm * 48 + im * 16 + (lane >> 2) + h * 8;
#pragma unroll
                for (int in = 0; in < 3; in++) {
                    int col = wn * 24 + in * 8 + (lane & 3) * 2;
                    *(float2*)(S + row * S_STRIDE + col) =
                        make_float2(c[im][in][h * 2], c[im][in][h * 2 + 1]);
                }
            }
    }
    __syncthreads();

#pragma unroll
    for (int r = 0; r < 12; r++) {
        int row = wid * 12 + r;
        float* p = S + row * S_STRIDE;
        float x[3];
#pragma unroll
        for (int j = 0; j < 3; j++) {
            int col = lane + j * 32;
            float s = p[col];
            x[j] = (col <= row) ? s * 0.0625f : (-32767.0f * 0.0625f);
        }
        float mx = fmaxf(x[0], fmaxf(x[1], x[2]));
#pragma unroll
        for (int o = 16; o > 0; o >>= 1) mx = fmaxf(mx, __shfl_xor_sync(0xffffffffu, mx, o));
        float e0 = __expf(x[0] - mx), e1 = __expf(x[1] - mx), e2 = __expf(x[2] - mx);
        float sum = e0 + e1 + e2;
#pragma unroll
        for (int o = 16; o > 0; o >>= 1) sum += __shfl_xor_sync(0xffffffffu, sum, o);
        float inv = 1.0f / sum;
        p[lane]      = tf2f(e0 * inv);
        p[lane + 32] = tf2f(e1 * inv);
        p[lane + 64] = tf2f(e2 * inv);
    }
    __syncthreads();

    const int bbi = head / Nn, nh = head % Nn;
    for (int n0 = 0; n0 < 256; n0 += 64) {
#pragma unroll
        for (int j = 0; j < 6; j++) {
            int idx = j * 256 + tid;
            int sr = idx >> 4, f4 = idx & 15;
            float4 vv = *(const float4*)(vh + sr * 256 + n0 + f4 * 4);
            int kt = sr >> 5, srl = sr & 31;
            int ni = f4 >> 1;
            int kii = srl >> 3;
            int regb = (srl >> 2) & 1;
            int lb = (f4 & 1) * 16 + (srl & 3);
            float* dst = &Vs[kt * 2048 + ((ni * 4 + kii) * 32) * 2 + regb];
            dst[(lb + 0) * 2]  = vv.x;
            dst[(lb + 4) * 2]  = vv.y;
            dst[(lb + 8) * 2]  = vv.z;
            dst[(lb + 12) * 2] = vv.w;
        }
        __syncthreads();

        float c[3][2][4] = {};
#pragma unroll
        for (int kt = 0; kt < 3; kt++) {
#pragma unroll
            for (int ks = 0; ks < 4; ks++) {
                uint32_t a[3][4], b[2][2];
#pragma unroll
                for (int im = 0; im < 3; im++) {
                    const float* ap = S + (wm * 48 + im * 16 + (lane >> 2)) * S_STRIDE
                                        + kt * 32 + ks * 8 + (lane & 3);
                    a[im][0] = __float_as_uint(ap[0]);
                    a[im][1] = __float_as_uint(ap[8 * S_STRIDE]);
                    a[im][2] = __float_as_uint(ap[4]);
                    a[im][3] = __float_as_uint(ap[8 * S_STRIDE + 4]);
                }
#pragma unroll
                for (int in = 0; in < 2; in++) {
                    float2 bv = *(const float2*)&Vs[kt * 2048 +
                        (((wn * 2 + in) * 4 + ks) * 32 + lane) * 2];
                    b[in][0] = __float_as_uint(bv.x); b[in][1] = __float_as_uint(bv.y);
                }
#pragma unroll
                for (int im = 0; im < 3; im++)
#pragma unroll
                    for (int in = 0; in < 2; in++)
                        mma8(c[im][in], a[im], b[in]);
            }
        }
#pragma unroll
        for (int im = 0; im < 3; im++)
#pragma unroll
            for (int h = 0; h < 2; h++) {
                int t = wm * 48 + im * 16 + (lane >> 2) + h * 8;
                long ob = ((long)(bbi * Tt + t) * Nn + nh) * 256;
#pragma unroll
                for (int in = 0; in < 2; in++) {
                    int f = n0 + wn * 16 + in * 8 + (lane & 3) * 2;
                    *(float2*)(g_bufY + ob + f) =
                        make_float2(tf2f(c[im][in][h * 2]), tf2f(c[im][in][h * 2 + 1]));
                }
            }
        __syncthreads();
    }
}

// =====================================================================
// ln_stats: per-row {mean, rstd} only (no output tensor).
// =====================================================================
__global__ __launch_bounds__(256) void ln_stats(const float* __restrict__ in) {
    long row = (long)blockIdx.x * 8 + (threadIdx.x >> 5);
    int lane = threadIdx.x & 31;
    const float* p = in + row * 256;
    float4 a = *(const float4*)(p + lane * 4);
    float4 b = *(const float4*)(p + 128 + lane * 4);
    float s = a.x + a.y + a.z + a.w + b.x + b.y + b.z + b.w;
    float q = a.x * a.x + a.y * a.y + a.z * a.z + a.w * a.w +
              b.x * b.x + b.y * b.y + b.z * b.z + b.w * b.w;
#pragma unroll
    for (int o = 16; o > 0; o >>= 1) {
        s += __shfl_xor_sync(0xffffffffu, s, o);
        q += __shfl_xor_sync(0xffffffffu, q, o);
    }
    if (lane == 0) {
        float mean = s * (1.0f / 256.0f);
        float var = q * (1.0f / 256.0f) - mean * mean;
        g_stats[row] = make_float2(mean, rsqrtf(var + 1e-5f));
    }
}

// =====================================================================
// Final LayerNorm (fp32 out).
// =====================================================================
__global__ __launch_bounds__(256) void ln_k(
    const float* __restrict__ in, float* __restrict__ outfp)
{
    long row = (long)blockIdx.x * 8 + (threadIdx.x >> 5);
    int lane = threadIdx.x & 31;
    const float* p = in + row * 256;
    float4 a = *(const float4*)(p + lane * 4);
    float4 b = *(const float4*)(p + 128 + lane * 4);
    float s = a.x + a.y + a.z + a.w + b.x + b.y + b.z + b.w;
    float q = a.x * a.x + a.y * a.y + a.z * a.z + a.w * a.w +
              b.x * b.x + b.y * b.y + b.z * b.z + b.w * b.w;
#pragma unroll
    for (int o = 16; o > 0; o >>= 1) {
        s += __shfl_xor_sync(0xffffffffu, s, o);
        q += __shfl_xor_sync(0xffffffffu, q, o);
    }
    float mean = s * (1.0f / 256.0f);
    float var = q * (1.0f / 256.0f) - mean * mean;
    float rs = rsqrtf(var + 1e-5f);
    float* op = outfp + row * 256;
    *(float4*)(op + lane * 4) =
        make_float4((a.x - mean) * rs, (a.y - mean) * rs, (a.z - mean) * rs, (a.w - mean) * rs);
    *(float4*)(op + 128 + lane * 4) =
        make_float4((b.x - mean) * rs, (b.y - mean) * rs, (b.z - mean) * rs, (b.w - mean) * rs);
}

// =====================================================================
extern "C" void kernel_launch(void* const* d_in, const int* in_sizes, int n_in,
                              void* d_out, int out_size) {
    const float* xl  = (const float*)d_in[0];
    const float* xh  = (const float*)d_in[1];
    const float* te  = (const float*)d_in[2];
    const float* Wq  = (const float*)d_in[3];
    const float* bq  = (const float*)d_in[4];
    const float* Wk  = (const float*)d_in[5];
    const float* bk  = (const float*)d_in[6];
    const float* Wv  = (const float*)d_in[7];
    const float* bv  = (const float*)d_in[8];
    const float* Wo  = (const float*)d_in[9];
    const float* bo  = (const float*)d_in[10];
    const float* Wf1 = (const float*)d_in[11];
    const float* bf1 = (const float*)d_in[12];
    const float* Wf2 = (const float*)d_in[13];
    const float* bf2 = (const float*)d_in[14];
    float* out = (float*)d_out;

    static bool init = false;
    static float *wbase, *bA, *bB, *bC, *bX, *bY, *pH, *pHH;
    static float2* stats;
    if (!init) {
        cudaFuncSetAttribute(gemm_p, cudaFuncAttributeMaxDynamicSharedMemorySize, GEMM_SMEM_P);
        cudaFuncSetAttribute(gemm_kv, cudaFuncAttributeMaxDynamicSharedMemorySize, GEMM_SMEM_KV);
        cudaFuncSetAttribute(gemm_r<0>, cudaFuncAttributeMaxDynamicSharedMemorySize, GEMM_SMEM_R);
        cudaFuncSetAttribute(gemm_r<1>, cudaFuncAttributeMaxDynamicSharedMemorySize, GEMM_SMEM_R);
        cudaFuncSetAttribute(attn_fused, cudaFuncAttributeMaxDynamicSharedMemorySize, ATTN_SMEM);
        cudaGetSymbolAddress((void**)&wbase, g_bufW);
        cudaGetSymbolAddress((void**)&bA, g_bufA);
        cudaGetSymbolAddress((void**)&bB, g_bufB);
        cudaGetSymbolAddress((void**)&bC, g_bufC);
        cudaGetSymbolAddress((void**)&bX, g_bufX);
        cudaGetSymbolAddress((void**)&bY, g_bufY);
        cudaGetSymbolAddress((void**)&pH, g_PH);
        cudaGetSymbolAddress((void**)&pHH, g_PHH);
        cudaGetSymbolAddress((void**)&stats, g_stats);
        init = true;
    }

    prep_x<<<Mtot / 64, 256>>>(xl, xh, te);
    pack_w6<<<1536, 256>>>(Wq, Wk, Wv, Wo, Wf1, Wf2);

    dim3 gg(Mtot / 64, 2);   // 4800 x 2 CTAs per dense GEMM

    // q = X @ Wq^T + bq            -> bufA [B,N,T,F], tf32-rounded
    gemm_r<0><<<gg, 256, GEMM_SMEM_R>>>(bX, wbase + 0 * 65536, bq, nullptr, nullptr,
                                        bA, nullptr, 0, 1, 1);
    // k,v in ONE pass over PH      -> bufB, bufC [B,N,T,F]
    gemm_kv<<<gg, 256, GEMM_SMEM_KV>>>(pH, wbase + 1 * 65536, wbase + 2 * 65536,
                                       bk, bv, bB, bC);

    attn_fused<<<HEADS, 256, ATTN_SMEM>>>();       // -> bufY row-major (tf32)

    // preLN1 = Y @ Wo^T + bo + X   -> bufA fp32 row-major
    gemm_r<0><<<gg, 256, GEMM_SMEM_R>>>(bY, wbase + 3 * 65536, bo, bX, nullptr,
                                        bA, nullptr, 0, 0, 0);
    // LN1 stats only (out1 never materialized)
    ln_stats<<<Mtot / 8, 256>>>(bA);

    // h = relu(LN(preLN1) @ Wf1^T + bf1) -> pHH packed (LN applied in A loads)
    gemm_r<1><<<gg, 256, GEMM_SMEM_R>>>(bA, wbase + 4 * 65536, bf1, nullptr, stats,
                                        nullptr, pHH, 1, 0, 0);
    // preLN2 = h @ Wf2^T + bf2 + LN(preLN1) -> bufB fp32
    gemm_p<<<gg, 256, GEMM_SMEM_P>>>(pHH, wbase + 5 * 65536, bf2, bA, stats, bB, 0, 0, 0);
    ln_k<<<Mtot / 8, 256>>>(bB, out);              // final LN -> d_out
}